// round 7
// baseline (speedup 1.0000x reference)
#include <cuda_runtime.h>
#include <cuda_bf16.h>

#define Bb 64
#define Tt 512
#define Ii 1024
#define Hh 1024
#define G3 3072

// ---------------- scratch (static device globals; no allocation) ----------------
static __device__ float g_gi[(size_t)Tt * Bb * G3];   // [t][b][3H], b_ih folded in
static __device__ float g_h[2][Bb * Hh];              // ping-pong hidden state
static __device__ float g_dm[Tt * Bb];                // [t][b] mask: done?0:1
static __device__ int   g_kind;                       // 1 = done is 1-byte, 0 = 4-byte

// ---------------- tf32 mma helpers ----------------
__device__ __forceinline__ unsigned f2tf(float x) {
    unsigned r; asm("cvt.rna.tf32.f32 %0, %1;" : "=r"(r) : "f"(x)); return r;
}
// m16n8k8 row.col f32.tf32.tf32.f32
// A: a0=(m=gid,k=tig) a1=(m=gid+8,k=tig) a2=(m=gid,k=tig+4) a3=(m=gid+8,k=tig+4)
// B: b0=(k=tig,n=gid) b1=(k=tig+4,n=gid)
// C: c0=(gid,tig*2) c1=(gid,tig*2+1) c2=(gid+8,tig*2) c3=(gid+8,tig*2+1)
__device__ __forceinline__ void mma8(float* c, const unsigned* a, const unsigned* b) {
    asm("mma.sync.aligned.m16n8k8.row.col.f32.tf32.tf32.f32 "
        "{%0,%1,%2,%3}, {%4,%5,%6,%7}, {%8,%9}, {%0,%1,%2,%3};"
        : "+f"(c[0]), "+f"(c[1]), "+f"(c[2]), "+f"(c[3])
        : "r"(a[0]), "r"(a[1]), "r"(a[2]), "r"(a[3]), "r"(b[0]), "r"(b[1]));
}

// ---------------- done-dtype detection (graph-safe, device-side) ----------------
// Scan first 8192 words (valid for both 1-byte [32768 B] and 4-byte [131072 B]).
__global__ void detect_kernel(const unsigned* __restrict__ w) {
    __shared__ int hif, f32f;
    if (threadIdx.x == 0) { hif = 0; f32f = 0; }
    __syncthreads();
    for (int i = threadIdx.x; i < 8192; i += blockDim.x) {
        unsigned v = w[i];
        if (v == 0x3F800000u) atomicOr(&f32f, 1);
        else if (v & 0xFFFFFF00u) atomicOr(&hif, 1);
    }
    __syncthreads();
    if (threadIdx.x == 0) g_kind = (!f32f && hif) ? 1 : 0;
}

__global__ void prep_kernel(const void* __restrict__ done, const float* __restrict__ hidden) {
    int i = blockIdx.x * blockDim.x + threadIdx.x;
    if (i < Tt * Bb) {
        int t = i / Bb, b = i - t * Bb;
        int src = b * Tt + t;   // done is [B,T]
        bool d;
        if (g_kind == 1) d = ((const unsigned char*)done)[src] != 0;
        else             d = ((const unsigned*)done)[src] != 0u;
        g_dm[i] = d ? 0.f : 1.f;
    }
    if (i < Bb * Hh) g_h[0][i] = hidden[i];
}

// ---------------- GEMM1: gi[t][b][:] = input[b][t][:] @ W_ih^T + b_ih ----------------
// M=32768 (rows m=b*512+t), N=3072, K=1024. CTA 128x128x32, 8 warps (2x4).
// Dynamic smem, double buffered, pad stride 36 words (conflict-free frag loads).
__global__ void __launch_bounds__(256) gemm1_kernel(
    const float* __restrict__ A, const float* __restrict__ W,
    const float* __restrict__ bih)
{
    extern __shared__ unsigned sm[];
    unsigned* As = sm;            // [2][128*36]
    unsigned* Bs = sm + 9216;     // [2][128*36]
    const int tid = threadIdx.x;
    const int lane = tid & 31, wid = tid >> 5;
    const int gid = lane >> 2, tig = lane & 3;
    const int wm = (wid >> 2) * 64, wn = (wid & 3) * 32;
    const int n0 = blockIdx.x * 128, m0 = blockIdx.y * 128;  // N fastest -> W_ih L2-resident
    const int r0 = tid >> 3, c4 = tid & 7;

    float c[4][4][4];
    #pragma unroll
    for (int i = 0; i < 4; i++)
        #pragma unroll
        for (int j = 0; j < 4; j++)
            #pragma unroll
            for (int k = 0; k < 4; k++) c[i][j][k] = 0.f;

    // prologue: k-tile 0 -> buffer 0
    #pragma unroll
    for (int i = 0; i < 4; i++) {
        int row = r0 + i * 32;
        float4 va = *(const float4*)&A[(size_t)(m0 + row) * Ii + c4 * 4];
        float4 vb = *(const float4*)&W[(size_t)(n0 + row) * Ii + c4 * 4];
        int ba = row * 36 + c4 * 4;
        As[ba] = f2tf(va.x); As[ba+1] = f2tf(va.y); As[ba+2] = f2tf(va.z); As[ba+3] = f2tf(va.w);
        Bs[ba] = f2tf(vb.x); Bs[ba+1] = f2tf(vb.y); Bs[ba+2] = f2tf(vb.z); Bs[ba+3] = f2tf(vb.w);
    }
    __syncthreads();

    for (int kt = 0; kt < 32; ++kt) {
        const int cur = (kt & 1) * 4608;
        float4 pa[4], pb[4];
        if (kt < 31) {
            int k0 = (kt + 1) * 32;
            #pragma unroll
            for (int i = 0; i < 4; i++) {
                int row = r0 + i * 32;
                pa[i] = *(const float4*)&A[(size_t)(m0 + row) * Ii + k0 + c4 * 4];
                pb[i] = *(const float4*)&W[(size_t)(n0 + row) * Ii + k0 + c4 * 4];
            }
        }
        #pragma unroll
        for (int kk = 0; kk < 32; kk += 8) {
            unsigned a[4][4], b[4][2];
            #pragma unroll
            for (int im = 0; im < 4; im++) {
                int base = cur + (wm + im * 16 + gid) * 36 + kk + tig;
                a[im][0] = As[base];       a[im][1] = As[base + 288];
                a[im][2] = As[base + 4];   a[im][3] = As[base + 292];
            }
            #pragma unroll
            for (int in = 0; in < 4; in++) {
                int base = cur + (wn + in * 8 + gid) * 36 + kk + tig;
                b[in][0] = Bs[base]; b[in][1] = Bs[base + 4];
            }
            #pragma unroll
            for (int im = 0; im < 4; im++)
                #pragma unroll
                for (int in = 0; in < 4; in++)
                    mma8(c[im][in], a[im], b[in]);
        }
        if (kt < 31) {
            const int nxt = ((kt + 1) & 1) * 4608;
            #pragma unroll
            for (int i = 0; i < 4; i++) {
                int row = r0 + i * 32;
                int ba = nxt + row * 36 + c4 * 4;
                As[ba] = f2tf(pa[i].x); As[ba+1] = f2tf(pa[i].y); As[ba+2] = f2tf(pa[i].z); As[ba+3] = f2tf(pa[i].w);
                Bs[ba] = f2tf(pb[i].x); Bs[ba+1] = f2tf(pb[i].y); Bs[ba+2] = f2tf(pb[i].z); Bs[ba+3] = f2tf(pb[i].w);
            }
            __syncthreads();
        }
    }

    // epilogue: +bias, transpose row m=(b*512+t) -> gi row (t*64+b)
    #pragma unroll
    for (int im = 0; im < 4; im++) {
        int mA = m0 + wm + im * 16 + gid;
        int mB = mA + 8;
        int rowA = (mA & 511) * Bb + (mA >> 9);
        int rowB = (mB & 511) * Bb + (mB >> 9);
        #pragma unroll
        for (int in = 0; in < 4; in++) {
            int cn = n0 + wn + in * 8 + tig * 2;
            float bx = bih[cn], by = bih[cn + 1];
            float2 v0 = make_float2(c[im][in][0] + bx, c[im][in][1] + by);
            float2 v1 = make_float2(c[im][in][2] + bx, c[im][in][3] + by);
            *(float2*)&g_gi[(size_t)rowA * G3 + cn] = v0;
            *(float2*)&g_gi[(size_t)rowB * G3 + cn] = v1;
        }
    }
}

// ---------------- per-timestep kernel ----------------
// 64 CTAs x 16 h-columns (=> 48 W_hh rows). 4 warps split the 64 batch rows.
// tf32 mma, K double-buffered in 32-chunks, done-mask folded into h smem load.
// Full gate math (sigmoid/tanh, fp32) in the same kernel; ping-pong h buffers.
__global__ void __launch_bounds__(128) step_kernel(
    const float* __restrict__ Whh, const float* __restrict__ bhh,
    float* __restrict__ outp, int t)
{
    __shared__ unsigned hs[2 * 2304];   // [2][64*36]
    __shared__ unsigned ws[2 * 1728];   // [2][48*36]
    __shared__ float dms[64];
    __shared__ float bsh[48];

    const float* __restrict__ h_in  = g_h[t & 1];
    float* __restrict__       h_out = g_h[(t + 1) & 1];
    const float* __restrict__ gi_t  = g_gi + (size_t)t * (Bb * G3);
    const float* __restrict__ dm_t  = g_dm + t * Bb;

    const int tid = threadIdx.x;
    const int lane = tid & 31, wid = tid >> 5;
    const int gid = lane >> 2, tig = lane & 3;
    const int col0 = blockIdx.x * 16;

    if (tid < 64) dms[tid] = dm_t[tid];
    if (tid < 48) bsh[tid] = bhh[(tid >> 4) * Hh + col0 + (tid & 15)];
    __syncthreads();

    float c[6][4];   // [gate*2 + ntile][frag]
    #pragma unroll
    for (int g = 0; g < 6; g++)
        #pragma unroll
        for (int s = 0; s < 4; s++) c[g][s] = 0.f;

    // prologue: k-chunk 0
    #pragma unroll
    for (int j = 0; j < 4; j++) {            // h: 64 rows x 8 float4 = 512
        int f = j * 128 + tid;
        int row = f >> 3, cc = f & 7;
        float4 v = *(const float4*)&h_in[row * Hh + cc * 4];
        float m = dms[row];
        int ba = row * 36 + cc * 4;
        hs[ba]   = f2tf(v.x * m); hs[ba+1] = f2tf(v.y * m);
        hs[ba+2] = f2tf(v.z * m); hs[ba+3] = f2tf(v.w * m);
    }
    #pragma unroll
    for (int j = 0; j < 3; j++) {            // W: 48 rows x 8 float4 = 384
        int f = j * 128 + tid;
        int row = f >> 3, cc = f & 7;
        float4 v = *(const float4*)&Whh[(size_t)((row >> 4) * Hh + col0 + (row & 15)) * Hh + cc * 4];
        int ba = row * 36 + cc * 4;
        ws[ba]   = f2tf(v.x); ws[ba+1] = f2tf(v.y);
        ws[ba+2] = f2tf(v.z); ws[ba+3] = f2tf(v.w);
    }
    __syncthreads();

    for (int kt = 0; kt < 32; ++kt) {
        const int curh = (kt & 1) * 2304, curw = (kt & 1) * 1728;
        float4 rh[4], rw[3];
        if (kt < 31) {
            int k0 = (kt + 1) * 32;
            #pragma unroll
            for (int j = 0; j < 4; j++) {
                int f = j * 128 + tid;
                int row = f >> 3, cc = f & 7;
                rh[j] = *(const float4*)&h_in[row * Hh + k0 + cc * 4];
            }
            #pragma unroll
            for (int j = 0; j < 3; j++) {
                int f = j * 128 + tid;
                int row = f >> 3, cc = f & 7;
                rw[j] = *(const float4*)&Whh[(size_t)((row >> 4) * Hh + col0 + (row & 15)) * Hh + k0 + cc * 4];
            }
        }
        #pragma unroll
        for (int kk = 0; kk < 32; kk += 8) {
            unsigned a[4];
            int ab = curh + (wid * 16 + gid) * 36 + kk + tig;
            a[0] = hs[ab];     a[1] = hs[ab + 288];
            a[2] = hs[ab + 4]; a[3] = hs[ab + 292];
            #pragma unroll
            for (int g = 0; g < 3; g++)
                #pragma unroll
                for (int nt = 0; nt < 2; nt++) {
                    unsigned b[2];
                    int bb = curw + (g * 16 + nt * 8 + gid) * 36 + kk + tig;
                    b[0] = ws[bb]; b[1] = ws[bb + 4];
                    mma8(c[g * 2 + nt], a, b);
                }
        }
        if (kt < 31) {
            const int nh = ((kt + 1) & 1) * 2304, nw = ((kt + 1) & 1) * 1728;
            #pragma unroll
            for (int j = 0; j < 4; j++) {
                int f = j * 128 + tid;
                int row = f >> 3, cc = f & 7;
                float m = dms[row];
                int ba = nh + row * 36 + cc * 4;
                hs[ba]   = f2tf(rh[j].x * m); hs[ba+1] = f2tf(rh[j].y * m);
                hs[ba+2] = f2tf(rh[j].z * m); hs[ba+3] = f2tf(rh[j].w * m);
            }
            #pragma unroll
            for (int j = 0; j < 3; j++) {
                int f = j * 128 + tid;
                int row = f >> 3, cc = f & 7;
                int ba = nw + row * 36 + cc * 4;
                ws[ba]   = f2tf(rw[j].x); ws[ba+1] = f2tf(rw[j].y);
                ws[ba+2] = f2tf(rw[j].z); ws[ba+3] = f2tf(rw[j].w);
            }
            __syncthreads();
        }
    }

    // gate math (fp32) + writes
    #pragma unroll
    for (int nt = 0; nt < 2; nt++)
        #pragma unroll
        for (int s = 0; s < 4; s++) {
            int b = wid * 16 + gid + ((s & 2) ? 8 : 0);
            int cc = nt * 8 + tig * 2 + (s & 1);
            int col = col0 + cc;
            float gr = c[nt][s]     + bsh[cc];
            float gz = c[2 + nt][s] + bsh[16 + cc];
            float gn = c[4 + nt][s] + bsh[32 + cc];
            const float* gi_b = gi_t + b * G3;
            float ir = gi_b[col], iz = gi_b[Hh + col], inn = gi_b[2 * Hh + col];
            float r = 1.f / (1.f + __expf(-(ir + gr)));
            float z = 1.f / (1.f + __expf(-(iz + gz)));
            float n = tanhf(inn + r * gn);
            float hm = h_in[b * Hh + col] * dms[b];
            float hn = (1.f - z) * n + z * hm;
            h_out[b * Hh + col] = hn;
            outp[((size_t)b * Tt + t) * Hh + col] = hn;
        }
}

__global__ void tail_kernel(float* __restrict__ dst) {
    int i = blockIdx.x * blockDim.x + threadIdx.x;
    if (i < Bb * Hh) dst[i] = g_h[0][i];   // after 512 steps, h_last lives in g_h[0]
}

extern "C" void kernel_launch(void* const* d_in, const int* in_sizes, int n_in,
                              void* d_out, int out_size) {
    const float* input  = (const float*)d_in[0];
    const float* hidden = (const float*)d_in[1];
    const void*  done   = d_in[2];
    const float* W_ih   = (const float*)d_in[3];
    const float* W_hh   = (const float*)d_in[4];
    const float* b_ih   = (const float*)d_in[5];
    const float* b_hh   = (const float*)d_in[6];
    float* out = (float*)d_out;

    cudaFuncSetAttribute(gemm1_kernel, cudaFuncAttributeMaxDynamicSharedMemorySize, 73728);

    detect_kernel<<<1, 256>>>((const unsigned*)done);
    prep_kernel<<<256, 256>>>(done, hidden);
    gemm1_kernel<<<dim3(G3 / 128, (Bb * Tt) / 128), 256, 73728>>>(input, W_ih, b_ih);
    for (int t = 0; t < Tt; ++t)
        step_kernel<<<Hh / 16, 128>>>(W_hh, b_hh, out, t);
    if (out_size >= Bb * Tt * Hh + Bb * Hh)
        tail_kernel<<<64, 1024>>>(out + (size_t)Bb * Tt * Hh);
}

// round 8
// speedup vs baseline: 1.5165x; 1.5165x over previous
#include <cuda_runtime.h>
#include <cuda_bf16.h>

#define Bb 64
#define Tt 512
#define Ii 1024
#define Hh 1024
#define G3 3072
#define NCTA 128
#define WSTR 1028   // W smem row stride (== 4 mod 32 -> conflict-free frags)

// ---------------- scratch (static device globals; no allocation) ----------------
static __device__ float g_gi[(size_t)Tt * Bb * G3];   // [t][b][3H], b_ih folded in
static __device__ float g_h[2][Bb * Hh];              // ping-pong hidden state
static __device__ float g_dm[Tt * Bb];                // [t][b] mask: done?0:1
static __device__ int   g_kind;                       // 1 = done is 1-byte, 0 = 4-byte
static __device__ unsigned g_bar;                     // grid barrier counter

// ---------------- tf32 mma helpers ----------------
__device__ __forceinline__ unsigned f2tf(float x) {
    unsigned r; asm("cvt.rna.tf32.f32 %0, %1;" : "=r"(r) : "f"(x)); return r;
}
// m16n8k8 row.col f32.tf32.tf32.f32
// A: a0=(m=gid,k=tig) a1=(m=gid+8,k=tig) a2=(m=gid,k=tig+4) a3=(m=gid+8,k=tig+4)
// B: b0=(k=tig,n=gid) b1=(k=tig+4,n=gid)
// C: c0=(gid,tig*2) c1=(gid,tig*2+1) c2=(gid+8,tig*2) c3=(gid+8,tig*2+1)
__device__ __forceinline__ void mma8(float* c, const unsigned* a, const unsigned* b) {
    asm("mma.sync.aligned.m16n8k8.row.col.f32.tf32.tf32.f32 "
        "{%0,%1,%2,%3}, {%4,%5,%6,%7}, {%8,%9}, {%0,%1,%2,%3};"
        : "+f"(c[0]), "+f"(c[1]), "+f"(c[2]), "+f"(c[3])
        : "r"(a[0]), "r"(a[1]), "r"(a[2]), "r"(a[3]), "r"(b[0]), "r"(b[1]));
}

// ---------------- done-dtype detection (graph-safe, device-side) ----------------
__global__ void detect_kernel(const unsigned* __restrict__ w) {
    __shared__ int hif, f32f;
    if (threadIdx.x == 0) { hif = 0; f32f = 0; }
    __syncthreads();
    for (int i = threadIdx.x; i < 8192; i += blockDim.x) {
        unsigned v = w[i];
        if (v == 0x3F800000u) atomicOr(&f32f, 1);
        else if (v & 0xFFFFFF00u) atomicOr(&hif, 1);
    }
    __syncthreads();
    if (threadIdx.x == 0) g_kind = (!f32f && hif) ? 1 : 0;
}

__global__ void prep_kernel(const void* __restrict__ done, const float* __restrict__ hidden) {
    int i = blockIdx.x * blockDim.x + threadIdx.x;
    if (i == 0) g_bar = 0u;
    if (i < Tt * Bb) {
        int t = i / Bb, b = i - t * Bb;
        int src = b * Tt + t;   // done is [B,T]
        bool d;
        if (g_kind == 1) d = ((const unsigned char*)done)[src] != 0;
        else             d = ((const unsigned*)done)[src] != 0u;
        g_dm[i] = d ? 0.f : 1.f;
    }
    if (i < Bb * Hh) g_h[0][i] = hidden[i];
}

// ---------------- GEMM1: gi[t][b][:] = input[b][t][:] @ W_ih^T + b_ih ----------------
__global__ void __launch_bounds__(256) gemm1_kernel(
    const float* __restrict__ A, const float* __restrict__ W,
    const float* __restrict__ bih)
{
    extern __shared__ unsigned sm[];
    unsigned* As = sm;            // [2][128*36]
    unsigned* Bs = sm + 9216;     // [2][128*36]
    const int tid = threadIdx.x;
    const int lane = tid & 31, wid = tid >> 5;
    const int gid = lane >> 2, tig = lane & 3;
    const int wm = (wid >> 2) * 64, wn = (wid & 3) * 32;
    const int n0 = blockIdx.x * 128, m0 = blockIdx.y * 128;  // N fastest -> W_ih L2-resident
    const int r0 = tid >> 3, c4 = tid & 7;

    float c[4][4][4];
    #pragma unroll
    for (int i = 0; i < 4; i++)
        #pragma unroll
        for (int j = 0; j < 4; j++)
            #pragma unroll
            for (int k = 0; k < 4; k++) c[i][j][k] = 0.f;

    #pragma unroll
    for (int i = 0; i < 4; i++) {
        int row = r0 + i * 32;
        float4 va = *(const float4*)&A[(size_t)(m0 + row) * Ii + c4 * 4];
        float4 vb = *(const float4*)&W[(size_t)(n0 + row) * Ii + c4 * 4];
        int ba = row * 36 + c4 * 4;
        As[ba] = f2tf(va.x); As[ba+1] = f2tf(va.y); As[ba+2] = f2tf(va.z); As[ba+3] = f2tf(va.w);
        Bs[ba] = f2tf(vb.x); Bs[ba+1] = f2tf(vb.y); Bs[ba+2] = f2tf(vb.z); Bs[ba+3] = f2tf(vb.w);
    }
    __syncthreads();

    for (int kt = 0; kt < 32; ++kt) {
        const int cur = (kt & 1) * 4608;
        float4 pa[4], pb[4];
        if (kt < 31) {
            int k0 = (kt + 1) * 32;
            #pragma unroll
            for (int i = 0; i < 4; i++) {
                int row = r0 + i * 32;
                pa[i] = *(const float4*)&A[(size_t)(m0 + row) * Ii + k0 + c4 * 4];
                pb[i] = *(const float4*)&W[(size_t)(n0 + row) * Ii + k0 + c4 * 4];
            }
        }
        #pragma unroll
        for (int kk = 0; kk < 32; kk += 8) {
            unsigned a[4][4], b[4][2];
            #pragma unroll
            for (int im = 0; im < 4; im++) {
                int base = cur + (wm + im * 16 + gid) * 36 + kk + tig;
                a[im][0] = As[base];       a[im][1] = As[base + 288];
                a[im][2] = As[base + 4];   a[im][3] = As[base + 292];
            }
            #pragma unroll
            for (int in = 0; in < 4; in++) {
                int base = cur + (wn + in * 8 + gid) * 36 + kk + tig;
                b[in][0] = Bs[base]; b[in][1] = Bs[base + 4];
            }
            #pragma unroll
            for (int im = 0; im < 4; im++)
                #pragma unroll
                for (int in = 0; in < 4; in++)
                    mma8(c[im][in], a[im], b[in]);
        }
        if (kt < 31) {
            const int nxt = ((kt + 1) & 1) * 4608;
            #pragma unroll
            for (int i = 0; i < 4; i++) {
                int row = r0 + i * 32;
                int ba = nxt + row * 36 + c4 * 4;
                As[ba] = f2tf(pa[i].x); As[ba+1] = f2tf(pa[i].y); As[ba+2] = f2tf(pa[i].z); As[ba+3] = f2tf(pa[i].w);
                Bs[ba] = f2tf(pb[i].x); Bs[ba+1] = f2tf(pb[i].y); Bs[ba+2] = f2tf(pb[i].z); Bs[ba+3] = f2tf(pb[i].w);
            }
            __syncthreads();
        }
    }

    #pragma unroll
    for (int im = 0; im < 4; im++) {
        int mA = m0 + wm + im * 16 + gid;
        int mB = mA + 8;
        int rowA = (mA & 511) * Bb + (mA >> 9);
        int rowB = (mB & 511) * Bb + (mB >> 9);
        #pragma unroll
        for (int in = 0; in < 4; in++) {
            int cn = n0 + wn + in * 8 + tig * 2;
            float bx = bih[cn], by = bih[cn + 1];
            float2 v0 = make_float2(c[im][in][0] + bx, c[im][in][1] + by);
            float2 v1 = make_float2(c[im][in][2] + bx, c[im][in][3] + by);
            *(float2*)&g_gi[(size_t)rowA * G3 + cn] = v0;
            *(float2*)&g_gi[(size_t)rowB * G3 + cn] = v1;
        }
    }
}

// ---------------- persistent recurrent kernel: all 512 steps ----------------
// 128 CTAs x 8 h-cols. W_hh slice (24 x 1024 tf32, 98.7KB) resident in smem.
// h streamed from L2 each step (ld.cg), done-mask folded in. Software grid
// barrier per step (all CTAs co-resident: 1 CTA/SM, grid 128 <= 148 SMs).
__global__ void __launch_bounds__(128, 1) rec_kernel(
    const float* __restrict__ Whh, const float* __restrict__ bhh,
    float* __restrict__ outp)
{
    extern __shared__ unsigned dyn[];
    unsigned* ws = dyn;                 // 24 * WSTR
    unsigned* hs = dyn + 24 * WSTR;     // 2 * 64*36
    __shared__ float dms[64];
    __shared__ float bsh[24];

    const int tid = threadIdx.x;
    const int lane = tid & 31, wid = tid >> 5;
    const int gid = lane >> 2, tig = lane & 3;
    const int col0 = blockIdx.x * 8;
    const int b0r = wid * 16 + gid;

    // Load W slice once: row r (gate r/8, col col0 + r%8), full K=1024, tf32.
    for (int f = tid; f < 24 * 256; f += 128) {
        int r = f >> 8, cq = f & 255;
        float4 v = *(const float4*)&Whh[(size_t)((r >> 3) * Hh + col0 + (r & 7)) * Hh + cq * 4];
        int ba = r * WSTR + cq * 4;
        ws[ba]   = f2tf(v.x); ws[ba+1] = f2tf(v.y);
        ws[ba+2] = f2tf(v.z); ws[ba+3] = f2tf(v.w);
    }
    if (tid < 24) bsh[tid] = bhh[(tid >> 3) * Hh + col0 + (tid & 7)];

    // This thread's own h entries (fragment layout), kept in regs across steps.
    float hloc[4];
    {
        int cb = col0 + tig * 2;
        hloc[0] = g_h[0][b0r * Hh + cb];
        hloc[1] = g_h[0][b0r * Hh + cb + 1];
        hloc[2] = g_h[0][(b0r + 8) * Hh + cb];
        hloc[3] = g_h[0][(b0r + 8) * Hh + cb + 1];
    }
    __syncthreads();

    for (int t = 0; t < Tt; ++t) {
        const float* __restrict__ h_in  = g_h[t & 1];
        float* __restrict__       h_out = g_h[(t + 1) & 1];
        const float* __restrict__ gi_t  = g_gi + (size_t)t * (Bb * G3);

        if (tid < 64) dms[tid] = g_dm[t * Bb + tid];
        __syncthreads();

        float c[3][4];
        #pragma unroll
        for (int g = 0; g < 3; g++)
            #pragma unroll
            for (int s = 0; s < 4; s++) c[g][s] = 0.f;

        // prologue: k-chunk 0 (ld.cg: L2-coherent across CTAs)
        #pragma unroll
        for (int j = 0; j < 4; j++) {
            int f = j * 128 + tid;
            int row = f >> 3, cc = f & 7;
            float4 v = __ldcg((const float4*)&h_in[row * Hh + cc * 4]);
            float m = dms[row];
            int ba = row * 36 + cc * 4;
            *(uint4*)&hs[ba] = make_uint4(f2tf(v.x*m), f2tf(v.y*m), f2tf(v.z*m), f2tf(v.w*m));
        }
        __syncthreads();

        for (int kt = 0; kt < 32; ++kt) {
            const int cur = (kt & 1) * 2304;
            float4 rh[4];
            if (kt < 31) {
                int k0 = (kt + 1) * 32;
                #pragma unroll
                for (int j = 0; j < 4; j++) {
                    int f = j * 128 + tid;
                    int row = f >> 3, cc = f & 7;
                    rh[j] = __ldcg((const float4*)&h_in[row * Hh + k0 + cc * 4]);
                }
            }
            #pragma unroll
            for (int kk = 0; kk < 32; kk += 8) {
                unsigned a[4];
                int ab = cur + b0r * 36 + kk + tig;
                a[0] = hs[ab];     a[1] = hs[ab + 288];
                a[2] = hs[ab + 4]; a[3] = hs[ab + 292];
                int k = kt * 32 + kk;
                #pragma unroll
                for (int g = 0; g < 3; g++) {
                    unsigned b[2];
                    int bb = (g * 8 + gid) * WSTR + k + tig;
                    b[0] = ws[bb]; b[1] = ws[bb + 4];
                    mma8(c[g], a, b);
                }
            }
            if (kt < 31) {
                const int nxt = ((kt + 1) & 1) * 2304;
                #pragma unroll
                for (int j = 0; j < 4; j++) {
                    int f = j * 128 + tid;
                    int row = f >> 3, cc = f & 7;
                    float m = dms[row];
                    int ba = nxt + row * 36 + cc * 4;
                    *(uint4*)&hs[ba] = make_uint4(f2tf(rh[j].x*m), f2tf(rh[j].y*m),
                                                  f2tf(rh[j].z*m), f2tf(rh[j].w*m));
                }
                __syncthreads();
            }
        }

        // gate math (fp32)
        float hn[4];
        #pragma unroll
        for (int s = 0; s < 4; s++) {
            int b = b0r + ((s & 2) ? 8 : 0);
            int cc = tig * 2 + (s & 1);
            int col = col0 + cc;
            float gr = c[0][s] + bsh[cc];
            float gz = c[1][s] + bsh[8 + cc];
            float gn = c[2][s] + bsh[16 + cc];
            const float* gi_b = gi_t + b * G3;
            float ir = gi_b[col], iz = gi_b[Hh + col], inn = gi_b[2 * Hh + col];
            float r = 1.f / (1.f + __expf(-(ir + gr)));
            float z = 1.f / (1.f + __expf(-(iz + gz)));
            float n = tanhf(inn + r * gn);
            float hm = hloc[s] * dms[b];
            hn[s] = (1.f - z) * n + z * hm;
            hloc[s] = hn[s];
        }
        {
            int cb = col0 + tig * 2;
            __stcg((float2*)&h_out[b0r * Hh + cb],       make_float2(hn[0], hn[1]));
            __stcg((float2*)&h_out[(b0r + 8) * Hh + cb], make_float2(hn[2], hn[3]));
            *(float2*)&outp[((size_t)b0r * Tt + t) * Hh + cb]       = make_float2(hn[0], hn[1]);
            *(float2*)&outp[((size_t)(b0r + 8) * Tt + t) * Hh + cb] = make_float2(hn[2], hn[3]);
        }

        // grid barrier: release h_out, arrive, spin until all CTAs arrived.
        __threadfence();
        __syncthreads();
        if (tid == 0) {
            atomicAdd(&g_bar, 1u);
            unsigned target = (unsigned)(t + 1) * (unsigned)gridDim.x;
            while (*(volatile unsigned*)&g_bar < target) { }
            __threadfence();
        }
        __syncthreads();
    }
}

__global__ void tail_kernel(float* __restrict__ dst) {
    int i = blockIdx.x * blockDim.x + threadIdx.x;
    if (i < Bb * Hh) dst[i] = g_h[0][i];   // after 512 steps, h_last lives in g_h[0]
}

extern "C" void kernel_launch(void* const* d_in, const int* in_sizes, int n_in,
                              void* d_out, int out_size) {
    const float* input  = (const float*)d_in[0];
    const float* hidden = (const float*)d_in[1];
    const void*  done   = d_in[2];
    const float* W_ih   = (const float*)d_in[3];
    const float* W_hh   = (const float*)d_in[4];
    const float* b_ih   = (const float*)d_in[5];
    const float* b_hh   = (const float*)d_in[6];
    float* out = (float*)d_out;

    const int rec_smem = (24 * WSTR + 2 * 64 * 36) * 4;  // 117120 B

    cudaFuncSetAttribute(gemm1_kernel, cudaFuncAttributeMaxDynamicSharedMemorySize, 73728);
    cudaFuncSetAttribute(rec_kernel, cudaFuncAttributeMaxDynamicSharedMemorySize, rec_smem);

    detect_kernel<<<1, 256>>>((const unsigned*)done);
    prep_kernel<<<256, 256>>>(done, hidden);
    gemm1_kernel<<<dim3(G3 / 128, (Bb * Tt) / 128), 256, 73728>>>(input, W_ih, b_ih);
    rec_kernel<<<NCTA, 128, rec_smem>>>(W_hh, b_hh, out);
    if (out_size >= Bb * Tt * Hh + Bb * Hh)
        tail_kernel<<<64, 1024>>>(out + (size_t)Bb * Tt * Hh);
}

// round 9
// speedup vs baseline: 2.4502x; 1.6157x over previous
#include <cuda_runtime.h>
#include <cuda_bf16.h>

#define Bb 64
#define Tt 512
#define Ii 1024
#define Hh 1024
#define G3 3072
#define NCTA 128
#define WSTR 1028   // W smem row stride (== 4 mod 32 -> conflict-free frags)

// ---------------- scratch (static device globals; no allocation) ----------------
static __device__ float g_gi[(size_t)Tt * Bb * G3];   // [t][b][3H], b_ih folded in
static __device__ float g_h[2][Bb * Hh];              // ping-pong hidden state
static __device__ float g_dm[Tt * Bb];                // [t][b] mask: done?0:1
static __device__ int   g_kind;                       // 1 = done is 1-byte, 0 = 4-byte
static __device__ unsigned g_bar;                     // grid barrier counter

// ---------------- tf32 mma helpers ----------------
__device__ __forceinline__ unsigned f2tf(float x) {
    unsigned r; asm("cvt.rna.tf32.f32 %0, %1;" : "=r"(r) : "f"(x)); return r;
}
// m16n8k8 row.col f32.tf32.tf32.f32
// A: a0=(m=gid,k=tig) a1=(m=gid+8,k=tig) a2=(m=gid,k=tig+4) a3=(m=gid+8,k=tig+4)
// B: b0=(k=tig,n=gid) b1=(k=tig+4,n=gid)
// C: c0=(gid,tig*2) c1=(gid,tig*2+1) c2=(gid+8,tig*2) c3=(gid+8,tig*2+1)
__device__ __forceinline__ void mma8(float* c, const unsigned* a, const unsigned* b) {
    asm("mma.sync.aligned.m16n8k8.row.col.f32.tf32.tf32.f32 "
        "{%0,%1,%2,%3}, {%4,%5,%6,%7}, {%8,%9}, {%0,%1,%2,%3};"
        : "+f"(c[0]), "+f"(c[1]), "+f"(c[2]), "+f"(c[3])
        : "r"(a[0]), "r"(a[1]), "r"(a[2]), "r"(a[3]), "r"(b[0]), "r"(b[1]));
}

// ---------------- done-dtype detection (graph-safe, device-side) ----------------
__global__ void detect_kernel(const unsigned* __restrict__ w) {
    __shared__ int hif, f32f;
    if (threadIdx.x == 0) { hif = 0; f32f = 0; }
    __syncthreads();
    for (int i = threadIdx.x; i < 8192; i += blockDim.x) {
        unsigned v = w[i];
        if (v == 0x3F800000u) atomicOr(&f32f, 1);
        else if (v & 0xFFFFFF00u) atomicOr(&hif, 1);
    }
    __syncthreads();
    if (threadIdx.x == 0) g_kind = (!f32f && hif) ? 1 : 0;
}

__global__ void prep_kernel(const void* __restrict__ done, const float* __restrict__ hidden) {
    int i = blockIdx.x * blockDim.x + threadIdx.x;
    if (i == 0) g_bar = 0u;
    if (i < Tt * Bb) {
        int t = i / Bb, b = i - t * Bb;
        int src = b * Tt + t;   // done is [B,T]
        bool d;
        if (g_kind == 1) d = ((const unsigned char*)done)[src] != 0;
        else             d = ((const unsigned*)done)[src] != 0u;
        g_dm[i] = d ? 0.f : 1.f;
    }
    if (i < Bb * Hh) g_h[0][i] = hidden[i];
}

// ---------------- GEMM1: gi[t][b][:] = input[b][t][:] @ W_ih^T + b_ih ----------------
__global__ void __launch_bounds__(256) gemm1_kernel(
    const float* __restrict__ A, const float* __restrict__ W,
    const float* __restrict__ bih)
{
    extern __shared__ unsigned sm[];
    unsigned* As = sm;            // [2][128*36]
    unsigned* Bs = sm + 9216;     // [2][128*36]
    const int tid = threadIdx.x;
    const int lane = tid & 31, wid = tid >> 5;
    const int gid = lane >> 2, tig = lane & 3;
    const int wm = (wid >> 2) * 64, wn = (wid & 3) * 32;
    const int n0 = blockIdx.x * 128, m0 = blockIdx.y * 128;  // N fastest -> W_ih L2-resident
    const int r0 = tid >> 3, c4 = tid & 7;

    float c[4][4][4];
    #pragma unroll
    for (int i = 0; i < 4; i++)
        #pragma unroll
        for (int j = 0; j < 4; j++)
            #pragma unroll
            for (int k = 0; k < 4; k++) c[i][j][k] = 0.f;

    #pragma unroll
    for (int i = 0; i < 4; i++) {
        int row = r0 + i * 32;
        float4 va = *(const float4*)&A[(size_t)(m0 + row) * Ii + c4 * 4];
        float4 vb = *(const float4*)&W[(size_t)(n0 + row) * Ii + c4 * 4];
        int ba = row * 36 + c4 * 4;
        As[ba] = f2tf(va.x); As[ba+1] = f2tf(va.y); As[ba+2] = f2tf(va.z); As[ba+3] = f2tf(va.w);
        Bs[ba] = f2tf(vb.x); Bs[ba+1] = f2tf(vb.y); Bs[ba+2] = f2tf(vb.z); Bs[ba+3] = f2tf(vb.w);
    }
    __syncthreads();

    for (int kt = 0; kt < 32; ++kt) {
        const int cur = (kt & 1) * 4608;
        float4 pa[4], pb[4];
        if (kt < 31) {
            int k0 = (kt + 1) * 32;
            #pragma unroll
            for (int i = 0; i < 4; i++) {
                int row = r0 + i * 32;
                pa[i] = *(const float4*)&A[(size_t)(m0 + row) * Ii + k0 + c4 * 4];
                pb[i] = *(const float4*)&W[(size_t)(n0 + row) * Ii + k0 + c4 * 4];
            }
        }
        #pragma unroll
        for (int kk = 0; kk < 32; kk += 8) {
            unsigned a[4][4], b[4][2];
            #pragma unroll
            for (int im = 0; im < 4; im++) {
                int base = cur + (wm + im * 16 + gid) * 36 + kk + tig;
                a[im][0] = As[base];       a[im][1] = As[base + 288];
                a[im][2] = As[base + 4];   a[im][3] = As[base + 292];
            }
            #pragma unroll
            for (int in = 0; in < 4; in++) {
                int base = cur + (wn + in * 8 + gid) * 36 + kk + tig;
                b[in][0] = Bs[base]; b[in][1] = Bs[base + 4];
            }
            #pragma unroll
            for (int im = 0; im < 4; im++)
                #pragma unroll
                for (int in = 0; in < 4; in++)
                    mma8(c[im][in], a[im], b[in]);
        }
        if (kt < 31) {
            const int nxt = ((kt + 1) & 1) * 4608;
            #pragma unroll
            for (int i = 0; i < 4; i++) {
                int row = r0 + i * 32;
                int ba = nxt + row * 36 + c4 * 4;
                As[ba] = f2tf(pa[i].x); As[ba+1] = f2tf(pa[i].y); As[ba+2] = f2tf(pa[i].z); As[ba+3] = f2tf(pa[i].w);
                Bs[ba] = f2tf(pb[i].x); Bs[ba+1] = f2tf(pb[i].y); Bs[ba+2] = f2tf(pb[i].z); Bs[ba+3] = f2tf(pb[i].w);
            }
            __syncthreads();
        }
    }

    #pragma unroll
    for (int im = 0; im < 4; im++) {
        int mA = m0 + wm + im * 16 + gid;
        int mB = mA + 8;
        int rowA = (mA & 511) * Bb + (mA >> 9);
        int rowB = (mB & 511) * Bb + (mB >> 9);
        #pragma unroll
        for (int in = 0; in < 4; in++) {
            int cn = n0 + wn + in * 8 + tig * 2;
            float bx = bih[cn], by = bih[cn + 1];
            float2 v0 = make_float2(c[im][in][0] + bx, c[im][in][1] + by);
            float2 v1 = make_float2(c[im][in][2] + bx, c[im][in][3] + by);
            *(float2*)&g_gi[(size_t)rowA * G3 + cn] = v0;
            *(float2*)&g_gi[(size_t)rowB * G3 + cn] = v1;
        }
    }
}

// ---------------- persistent recurrent kernel: all 512 steps ----------------
// 128 CTAs x 8 h-cols. W_hh slice resident in smem (tf32). h streamed from L2
// each step via a 4-stage cp.async.cg pipeline (raw fp32 -> tf32 by truncation).
// done-mask applied POST-GEMM (row scaling commutes with h@W^T). gi values
// prefetched at step start. Software grid barrier per step.
__global__ void __launch_bounds__(128, 1) rec_kernel(
    const float* __restrict__ Whh, const float* __restrict__ bhh,
    float* __restrict__ outp)
{
    extern __shared__ unsigned dyn[];
    unsigned* ws = dyn;                          // 24 * WSTR (tf32)
    unsigned* hsu = dyn + 24 * WSTR;             // 4 stages x 64*36 raw fp32 bits
    __shared__ float dms[64];
    __shared__ float bsh[24];

    const int tid = threadIdx.x;
    const int lane = tid & 31, wid = tid >> 5;
    const int gid = lane >> 2, tig = lane & 3;
    const int col0 = blockIdx.x * 8;
    const int b0r = wid * 16 + gid;
    const unsigned hs_u32 = (unsigned)__cvta_generic_to_shared(hsu);

    // Load W slice once: row r = (gate r/8, col col0 + r%8), K=1024, tf32.
    for (int f = tid; f < 24 * 256; f += 128) {
        int r = f >> 8, cq = f & 255;
        float4 v = *(const float4*)&Whh[(size_t)((r >> 3) * Hh + col0 + (r & 7)) * Hh + cq * 4];
        int ba = r * WSTR + cq * 4;
        ws[ba]   = f2tf(v.x); ws[ba+1] = f2tf(v.y);
        ws[ba+2] = f2tf(v.z); ws[ba+3] = f2tf(v.w);
    }
    if (tid < 24) bsh[tid] = bhh[(tid >> 3) * Hh + col0 + (tid & 7)];

    // This thread's own h entries (fragment layout), kept in regs across steps.
    float hloc[4];
    {
        int cb = col0 + tig * 2;
        hloc[0] = g_h[0][b0r * Hh + cb];
        hloc[1] = g_h[0][b0r * Hh + cb + 1];
        hloc[2] = g_h[0][(b0r + 8) * Hh + cb];
        hloc[3] = g_h[0][(b0r + 8) * Hh + cb + 1];
    }
    __syncthreads();

#define ISSUE_CHUNK(ch) do {                                                     \
        int _st = (ch) & 3;                                                      \
        _Pragma("unroll")                                                        \
        for (int _j = 0; _j < 4; _j++) {                                         \
            int _f = _j * 128 + tid, _row = _f >> 3, _cc = _f & 7;               \
            unsigned _dst = hs_u32 + ((unsigned)(_st * 2304 + _row * 36 + _cc * 4) << 2); \
            const float* _src = h_in + _row * Hh + (ch) * 32 + _cc * 4;          \
            asm volatile("cp.async.cg.shared.global [%0], [%1], 16;"             \
                         :: "r"(_dst), "l"(_src));                               \
        }                                                                        \
        asm volatile("cp.async.commit_group;");                                  \
    } while (0)

    for (int t = 0; t < Tt; ++t) {
        const float* __restrict__ h_in  = g_h[t & 1];
        float* __restrict__       h_out = g_h[(t + 1) & 1];
        const float* __restrict__ gi_t  = g_gi + (size_t)t * (Bb * G3);

        if (tid < 64) dms[tid] = g_dm[t * Bb + tid];

        // prefetch this thread's 12 gi values (independent of h; hides DRAM lat)
        float gpre[12];   // [row(0/1)][gate][col 0/1]
        {
            int cb = col0 + tig * 2;
            const float* g0 = gi_t + (size_t)b0r * G3;
            const float* g1 = gi_t + (size_t)(b0r + 8) * G3;
            #pragma unroll
            for (int g = 0; g < 3; g++) {
                gpre[g * 2]     = __ldcg(g0 + g * Hh + cb);
                gpre[g * 2 + 1] = __ldcg(g0 + g * Hh + cb + 1);
                gpre[6 + g * 2]     = __ldcg(g1 + g * Hh + cb);
                gpre[6 + g * 2 + 1] = __ldcg(g1 + g * Hh + cb + 1);
            }
        }

        // pipeline prologue: chunks 0..2 in flight
        ISSUE_CHUNK(0); ISSUE_CHUNK(1); ISSUE_CHUNK(2);

        float c[3][4];
        #pragma unroll
        for (int g = 0; g < 3; g++)
            #pragma unroll
            for (int s = 0; s < 4; s++) c[g][s] = 0.f;

        #pragma unroll 1
        for (int kt = 0; kt < 32; ++kt) {
            if (kt < 30)       asm volatile("cp.async.wait_group 2;");
            else if (kt == 30) asm volatile("cp.async.wait_group 1;");
            else               asm volatile("cp.async.wait_group 0;");
            __syncthreads();
            if (kt + 3 < 32) ISSUE_CHUNK(kt + 3);

            const int cur = (kt & 3) * 2304;
            #pragma unroll
            for (int kk = 0; kk < 32; kk += 8) {
                unsigned a[4];
                int ab = cur + b0r * 36 + kk + tig;
                a[0] = hsu[ab];     a[1] = hsu[ab + 288];
                a[2] = hsu[ab + 4]; a[3] = hsu[ab + 292];
                int k = kt * 32 + kk;
                #pragma unroll
                for (int g = 0; g < 3; g++) {
                    unsigned b[2];
                    int bb = (g * 8 + gid) * WSTR + k + tig;
                    b[0] = ws[bb]; b[1] = ws[bb + 4];
                    mma8(c[g], a, b);
                }
            }
        }

        // gate math (fp32); done-mask applied to matmul part + old h
        float hn[4];
        #pragma unroll
        for (int s = 0; s < 4; s++) {
            int r = s >> 1, i = s & 1;
            int b = b0r + r * 8;
            int cc = tig * 2 + i;
            float mb = dms[b];
            float gr = c[0][s] * mb + bsh[cc];
            float gz = c[1][s] * mb + bsh[8 + cc];
            float gn = c[2][s] * mb + bsh[16 + cc];
            float rg = 1.f / (1.f + __expf(-(gpre[r * 6 + i] + gr)));
            float zg = 1.f / (1.f + __expf(-(gpre[r * 6 + 2 + i] + gz)));
            float ng = tanhf(gpre[r * 6 + 4 + i] + rg * gn);
            float hm = hloc[s] * mb;
            hn[s] = (1.f - zg) * ng + zg * hm;
            hloc[s] = hn[s];
        }
        {
            int cb = col0 + tig * 2;
            __stcg((float2*)&h_out[b0r * Hh + cb],       make_float2(hn[0], hn[1]));
            __stcg((float2*)&h_out[(b0r + 8) * Hh + cb], make_float2(hn[2], hn[3]));
            __stcs((float2*)&outp[((size_t)b0r * Tt + t) * Hh + cb],       make_float2(hn[0], hn[1]));
            __stcs((float2*)&outp[((size_t)(b0r + 8) * Tt + t) * Hh + cb], make_float2(hn[2], hn[3]));
        }

        // grid barrier: release h_out, arrive, spin until all CTAs arrived.
        __threadfence();
        __syncthreads();
        if (tid == 0) {
            atomicAdd(&g_bar, 1u);
            unsigned target = (unsigned)(t + 1) * (unsigned)gridDim.x;
            while (*(volatile unsigned*)&g_bar < target) { }
            __threadfence();
        }
        __syncthreads();
    }
#undef ISSUE_CHUNK
}

__global__ void tail_kernel(float* __restrict__ dst) {
    int i = blockIdx.x * blockDim.x + threadIdx.x;
    if (i < Bb * Hh) dst[i] = g_h[0][i];   // after 512 steps, h_last lives in g_h[0]
}

extern "C" void kernel_launch(void* const* d_in, const int* in_sizes, int n_in,
                              void* d_out, int out_size) {
    const float* input  = (const float*)d_in[0];
    const float* hidden = (const float*)d_in[1];
    const void*  done   = d_in[2];
    const float* W_ih   = (const float*)d_in[3];
    const float* W_hh   = (const float*)d_in[4];
    const float* b_ih   = (const float*)d_in[5];
    const float* b_hh   = (const float*)d_in[6];
    float* out = (float*)d_out;

    const int rec_smem = (24 * WSTR + 4 * 64 * 36) * 4;  // 135552 B

    cudaFuncSetAttribute(gemm1_kernel, cudaFuncAttributeMaxDynamicSharedMemorySize, 73728);
    cudaFuncSetAttribute(rec_kernel, cudaFuncAttributeMaxDynamicSharedMemorySize, rec_smem);

    detect_kernel<<<1, 256>>>((const unsigned*)done);
    prep_kernel<<<256, 256>>>(done, hidden);
    gemm1_kernel<<<dim3(G3 / 128, (Bb * Tt) / 128), 256, 73728>>>(input, W_ih, b_ih);
    rec_kernel<<<NCTA, 128, rec_smem>>>(W_hh, b_hh, out);
    if (out_size >= Bb * Tt * Hh + Bb * Hh)
        tail_kernel<<<64, 1024>>>(out + (size_t)Bb * Tt * Hh);
}

// round 10
// speedup vs baseline: 2.5608x; 1.0451x over previous
#include <cuda_runtime.h>
#include <cuda_bf16.h>

#define Bb 64
#define Tt 512
#define Ii 1024
#define Hh 1024
#define G3 3072
#define NCTA 128
#define WSTR 1028   // W smem row stride (== 4 mod 32 -> conflict-free frags)

// ---------------- scratch (static device globals; no allocation) ----------------
static __device__ float g_gi[(size_t)Tt * Bb * G3];   // [t][b][3H], b_ih folded in
static __device__ float g_h[2][Bb * Hh];              // ping-pong hidden state
static __device__ float g_dm[Tt * Bb];                // [t][b] mask: done?0:1
static __device__ int   g_kind;                       // 1 = done is 1-byte, 0 = 4-byte
static __device__ unsigned g_bar;                     // grid barrier counter

// ---------------- tf32 mma helpers ----------------
__device__ __forceinline__ unsigned f2tf(float x) {
    unsigned r; asm("cvt.rna.tf32.f32 %0, %1;" : "=r"(r) : "f"(x)); return r;
}
// m16n8k8 row.col f32.tf32.tf32.f32
// A: a0=(m=gid,k=tig) a1=(m=gid+8,k=tig) a2=(m=gid,k=tig+4) a3=(m=gid+8,k=tig+4)
// B: b0=(k=tig,n=gid) b1=(k=tig+4,n=gid)
// C: c0=(gid,tig*2) c1=(gid,tig*2+1) c2=(gid+8,tig*2) c3=(gid+8,tig*2+1)
__device__ __forceinline__ void mma8(float* c, const unsigned* a, const unsigned* b) {
    asm("mma.sync.aligned.m16n8k8.row.col.f32.tf32.tf32.f32 "
        "{%0,%1,%2,%3}, {%4,%5,%6,%7}, {%8,%9}, {%0,%1,%2,%3};"
        : "+f"(c[0]), "+f"(c[1]), "+f"(c[2]), "+f"(c[3])
        : "r"(a[0]), "r"(a[1]), "r"(a[2]), "r"(a[3]), "r"(b[0]), "r"(b[1]));
}

// ---------------- done-dtype detection (graph-safe, device-side) ----------------
__global__ void detect_kernel(const unsigned* __restrict__ w) {
    __shared__ int hif, f32f;
    if (threadIdx.x == 0) { hif = 0; f32f = 0; }
    __syncthreads();
    for (int i = threadIdx.x; i < 8192; i += blockDim.x) {
        unsigned v = w[i];
        if (v == 0x3F800000u) atomicOr(&f32f, 1);
        else if (v & 0xFFFFFF00u) atomicOr(&hif, 1);
    }
    __syncthreads();
    if (threadIdx.x == 0) g_kind = (!f32f && hif) ? 1 : 0;
}

__global__ void prep_kernel(const void* __restrict__ done, const float* __restrict__ hidden) {
    int i = blockIdx.x * blockDim.x + threadIdx.x;
    if (i == 0) g_bar = 0u;
    if (i < Tt * Bb) {
        int t = i / Bb, b = i - t * Bb;
        int src = b * Tt + t;   // done is [B,T]
        bool d;
        if (g_kind == 1) d = ((const unsigned char*)done)[src] != 0;
        else             d = ((const unsigned*)done)[src] != 0u;
        g_dm[i] = d ? 0.f : 1.f;
    }
    if (i < Bb * Hh) g_h[0][i] = hidden[i];
}

// ---------------- GEMM1: gi[t][b][:] = input[b][t][:] @ W_ih^T + b_ih ----------------
__global__ void __launch_bounds__(256) gemm1_kernel(
    const float* __restrict__ A, const float* __restrict__ W,
    const float* __restrict__ bih)
{
    extern __shared__ unsigned sm[];
    unsigned* As = sm;            // [2][128*36]
    unsigned* Bs = sm + 9216;     // [2][128*36]
    const int tid = threadIdx.x;
    const int lane = tid & 31, wid = tid >> 5;
    const int gid = lane >> 2, tig = lane & 3;
    const int wm = (wid >> 2) * 64, wn = (wid & 3) * 32;
    const int n0 = blockIdx.x * 128, m0 = blockIdx.y * 128;  // N fastest -> W_ih L2-resident
    const int r0 = tid >> 3, c4 = tid & 7;

    float c[4][4][4];
    #pragma unroll
    for (int i = 0; i < 4; i++)
        #pragma unroll
        for (int j = 0; j < 4; j++)
            #pragma unroll
            for (int k = 0; k < 4; k++) c[i][j][k] = 0.f;

    #pragma unroll
    for (int i = 0; i < 4; i++) {
        int row = r0 + i * 32;
        float4 va = *(const float4*)&A[(size_t)(m0 + row) * Ii + c4 * 4];
        float4 vb = *(const float4*)&W[(size_t)(n0 + row) * Ii + c4 * 4];
        int ba = row * 36 + c4 * 4;
        As[ba] = f2tf(va.x); As[ba+1] = f2tf(va.y); As[ba+2] = f2tf(va.z); As[ba+3] = f2tf(va.w);
        Bs[ba] = f2tf(vb.x); Bs[ba+1] = f2tf(vb.y); Bs[ba+2] = f2tf(vb.z); Bs[ba+3] = f2tf(vb.w);
    }
    __syncthreads();

    for (int kt = 0; kt < 32; ++kt) {
        const int cur = (kt & 1) * 4608;
        float4 pa[4], pb[4];
        if (kt < 31) {
            int k0 = (kt + 1) * 32;
            #pragma unroll
            for (int i = 0; i < 4; i++) {
                int row = r0 + i * 32;
                pa[i] = *(const float4*)&A[(size_t)(m0 + row) * Ii + k0 + c4 * 4];
                pb[i] = *(const float4*)&W[(size_t)(n0 + row) * Ii + k0 + c4 * 4];
            }
        }
        #pragma unroll
        for (int kk = 0; kk < 32; kk += 8) {
            unsigned a[4][4], b[4][2];
            #pragma unroll
            for (int im = 0; im < 4; im++) {
                int base = cur + (wm + im * 16 + gid) * 36 + kk + tig;
                a[im][0] = As[base];       a[im][1] = As[base + 288];
                a[im][2] = As[base + 4];   a[im][3] = As[base + 292];
            }
            #pragma unroll
            for (int in = 0; in < 4; in++) {
                int base = cur + (wn + in * 8 + gid) * 36 + kk + tig;
                b[in][0] = Bs[base]; b[in][1] = Bs[base + 4];
            }
            #pragma unroll
            for (int im = 0; im < 4; im++)
                #pragma unroll
                for (int in = 0; in < 4; in++)
                    mma8(c[im][in], a[im], b[in]);
        }
        if (kt < 31) {
            const int nxt = ((kt + 1) & 1) * 4608;
            #pragma unroll
            for (int i = 0; i < 4; i++) {
                int row = r0 + i * 32;
                int ba = nxt + row * 36 + c4 * 4;
                As[ba] = f2tf(pa[i].x); As[ba+1] = f2tf(pa[i].y); As[ba+2] = f2tf(pa[i].z); As[ba+3] = f2tf(pa[i].w);
                Bs[ba] = f2tf(pb[i].x); Bs[ba+1] = f2tf(pb[i].y); Bs[ba+2] = f2tf(pb[i].z); Bs[ba+3] = f2tf(pb[i].w);
            }
            __syncthreads();
        }
    }

    #pragma unroll
    for (int im = 0; im < 4; im++) {
        int mA = m0 + wm + im * 16 + gid;
        int mB = mA + 8;
        int rowA = (mA & 511) * Bb + (mA >> 9);
        int rowB = (mB & 511) * Bb + (mB >> 9);
        #pragma unroll
        for (int in = 0; in < 4; in++) {
            int cn = n0 + wn + in * 8 + tig * 2;
            float bx = bih[cn], by = bih[cn + 1];
            float2 v0 = make_float2(c[im][in][0] + bx, c[im][in][1] + by);
            float2 v1 = make_float2(c[im][in][2] + bx, c[im][in][3] + by);
            *(float2*)&g_gi[(size_t)rowA * G3 + cn] = v0;
            *(float2*)&g_gi[(size_t)rowB * G3 + cn] = v1;
        }
    }
}

// ---------------- persistent recurrent kernel: all 512 steps ----------------
// 128 CTAs x 8 h-cols, 256 threads = 8 warps, K-SPLIT: warps 0-3 do K[0,512),
// warps 4-7 do K[512,1024); partials reduced via smem at step end.
// W_hh slice resident in smem (tf32). h streamed from L2 each step via 4-stage
// cp.async.cg super-chunk pipeline (each stage holds a 32-K slice per group).
// done-mask applied POST-GEMM. Software grid barrier per step.
__global__ void __launch_bounds__(256, 1) rec_kernel(
    const float* __restrict__ Whh, const float* __restrict__ bhh,
    float* __restrict__ outp)
{
    extern __shared__ unsigned dyn[];
    unsigned* ws = dyn;                          // 24 * WSTR (tf32)
    unsigned* hsu = dyn + 24 * WSTR;             // 4 stages x [2 groups x 64*36] fp32 bits
    float* red = (float*)hsu;                    // reduction scratch (reused)
    __shared__ float dms[64];
    __shared__ float bsh[24];

    const int tid = threadIdx.x;
    const int lane = tid & 31, wid = tid >> 5;
    const int gid = lane >> 2, tig = lane & 3;
    const int ks = wid >> 2;                     // K-split group 0/1
    const int col0 = blockIdx.x * 8;
    const int b0r = (wid & 3) * 16 + gid;
    const unsigned hs_u32 = (unsigned)__cvta_generic_to_shared(hsu);

    // Load W slice once: row r = (gate r/8, col col0 + r%8), K=1024, tf32.
    for (int f = tid; f < 24 * 256; f += 256) {
        int r = f >> 8, cq = f & 255;
        float4 v = *(const float4*)&Whh[(size_t)((r >> 3) * Hh + col0 + (r & 7)) * Hh + cq * 4];
        int ba = r * WSTR + cq * 4;
        ws[ba]   = f2tf(v.x); ws[ba+1] = f2tf(v.y);
        ws[ba+2] = f2tf(v.z); ws[ba+3] = f2tf(v.w);
    }
    if (tid < 24) bsh[tid] = bhh[(tid >> 3) * Hh + col0 + (tid & 7)];

    // Warps 0-3: this thread's own h entries (fragment layout), in regs across steps.
    float hloc[4] = {0.f, 0.f, 0.f, 0.f};
    if (tid < 128) {
        int cb = col0 + tig * 2;
        hloc[0] = g_h[0][b0r * Hh + cb];
        hloc[1] = g_h[0][b0r * Hh + cb + 1];
        hloc[2] = g_h[0][(b0r + 8) * Hh + cb];
        hloc[3] = g_h[0][(b0r + 8) * Hh + cb + 1];
    }
    __syncthreads();

// super-chunk ch: group0 K-range [ch*32,+32), group1 [512+ch*32,+32); one commit group
#define ISSUE_CHUNK(ch) do {                                                     \
        unsigned _base = hs_u32 + ((unsigned)(((ch) & 3) * 4608) << 2);          \
        _Pragma("unroll")                                                        \
        for (int _j = 0; _j < 2; _j++) {                                         \
            int _f = _j * 256 + tid, _row = _f >> 3, _cc = _f & 7;               \
            unsigned _dst = _base + ((unsigned)(_row * 36 + _cc * 4) << 2);      \
            const float* _src = h_in + _row * Hh + (ch) * 32 + _cc * 4;          \
            asm volatile("cp.async.cg.shared.global [%0], [%1], 16;"             \
                         :: "r"(_dst), "l"(_src));                               \
            asm volatile("cp.async.cg.shared.global [%0], [%1], 16;"             \
                         :: "r"(_dst + (2304u << 2)), "l"(_src + 512));          \
        }                                                                        \
        asm volatile("cp.async.commit_group;");                                  \
    } while (0)

    for (int t = 0; t < Tt; ++t) {
        const float* __restrict__ h_in  = g_h[t & 1];
        float* __restrict__       h_out = g_h[(t + 1) & 1];
        const float* __restrict__ gi_t  = g_gi + (size_t)t * (Bb * G3);

        if (tid < 64) dms[tid] = g_dm[t * Bb + tid];

        // warps 0-3: prefetch gi (independent of h; hides DRAM latency)
        float gpre[12];
        if (tid < 128) {
            int cb = col0 + tig * 2;
            const float* g0 = gi_t + (size_t)b0r * G3;
            const float* g1 = gi_t + (size_t)(b0r + 8) * G3;
            #pragma unroll
            for (int g = 0; g < 3; g++) {
                gpre[g * 2]         = __ldcg(g0 + g * Hh + cb);
                gpre[g * 2 + 1]     = __ldcg(g0 + g * Hh + cb + 1);
                gpre[6 + g * 2]     = __ldcg(g1 + g * Hh + cb);
                gpre[6 + g * 2 + 1] = __ldcg(g1 + g * Hh + cb + 1);
            }
        }

        ISSUE_CHUNK(0); ISSUE_CHUNK(1); ISSUE_CHUNK(2);

        float c[3][4];
        #pragma unroll
        for (int g = 0; g < 3; g++)
            #pragma unroll
            for (int s = 0; s < 4; s++) c[g][s] = 0.f;

        #pragma unroll 1
        for (int i = 0; i < 16; ++i) {
            if (i < 14)       asm volatile("cp.async.wait_group 2;");
            else if (i == 14) asm volatile("cp.async.wait_group 1;");
            else              asm volatile("cp.async.wait_group 0;");
            __syncthreads();
            if (i + 3 < 16) ISSUE_CHUNK(i + 3);

            const int cur = (i & 3) * 4608 + ks * 2304;
            const int kb = ks * 512 + i * 32;
            #pragma unroll
            for (int kk = 0; kk < 32; kk += 8) {
                unsigned a[4];
                int ab = cur + b0r * 36 + kk + tig;
                a[0] = hsu[ab];     a[1] = hsu[ab + 288];
                a[2] = hsu[ab + 4]; a[3] = hsu[ab + 292];
                #pragma unroll
                for (int g = 0; g < 3; g++) {
                    unsigned b[2];
                    int bb = (g * 8 + gid) * WSTR + kb + kk + tig;
                    b[0] = ws[bb]; b[1] = ws[bb + 4];
                    mma8(c[g], a, b);
                }
            }
        }

        // K-split reduction: warps 4-7 park partials in smem, warps 0-3 add.
        __syncthreads();
        if (tid >= 128) {
            int base = (tid - 128) * 13;
            #pragma unroll
            for (int g = 0; g < 3; g++)
                #pragma unroll
                for (int s = 0; s < 4; s++) red[base + g * 4 + s] = c[g][s];
        }
        __syncthreads();

        if (tid < 128) {
            int base = tid * 13;
            float hn[4];
            #pragma unroll
            for (int s = 0; s < 4; s++) {
                int r = s >> 1, i = s & 1;
                int b = b0r + r * 8;
                int cc = tig * 2 + i;
                float mb = dms[b];
                float gr = (c[0][s] + red[base + s])     * mb + bsh[cc];
                float gz = (c[1][s] + red[base + 4 + s]) * mb + bsh[8 + cc];
                float gn = (c[2][s] + red[base + 8 + s]) * mb + bsh[16 + cc];
                float rg = 1.f / (1.f + __expf(-(gpre[r * 6 + i] + gr)));
                float zg = 1.f / (1.f + __expf(-(gpre[r * 6 + 2 + i] + gz)));
                float ng = tanhf(gpre[r * 6 + 4 + i] + rg * gn);
                float hm = hloc[s] * mb;
                hn[s] = (1.f - zg) * ng + zg * hm;
                hloc[s] = hn[s];
            }
            int cb = col0 + tig * 2;
            __stcg((float2*)&h_out[b0r * Hh + cb],       make_float2(hn[0], hn[1]));
            __stcg((float2*)&h_out[(b0r + 8) * Hh + cb], make_float2(hn[2], hn[3]));
            __stcs((float2*)&outp[((size_t)b0r * Tt + t) * Hh + cb],       make_float2(hn[0], hn[1]));
            __stcs((float2*)&outp[((size_t)(b0r + 8) * Tt + t) * Hh + cb], make_float2(hn[2], hn[3]));
        }

        // grid barrier: release h_out, arrive, spin until all CTAs arrived.
        __threadfence();
        __syncthreads();
        if (tid == 0) {
            atomicAdd(&g_bar, 1u);
            unsigned target = (unsigned)(t + 1) * (unsigned)gridDim.x;
            while (*(volatile unsigned*)&g_bar < target) { }
            __threadfence();
        }
        __syncthreads();
    }
#undef ISSUE_CHUNK
}

__global__ void tail_kernel(float* __restrict__ dst) {
    int i = blockIdx.x * blockDim.x + threadIdx.x;
    if (i < Bb * Hh) dst[i] = g_h[0][i];   // after 512 steps, h_last lives in g_h[0]
}

extern "C" void kernel_launch(void* const* d_in, const int* in_sizes, int n_in,
                              void* d_out, int out_size) {
    const float* input  = (const float*)d_in[0];
    const float* hidden = (const float*)d_in[1];
    const void*  done   = d_in[2];
    const float* W_ih   = (const float*)d_in[3];
    const float* W_hh   = (const float*)d_in[4];
    const float* b_ih   = (const float*)d_in[5];
    const float* b_hh   = (const float*)d_in[6];
    float* out = (float*)d_out;

    const int rec_smem = (24 * WSTR + 4 * 4608) * 4;  // 172416 B

    cudaFuncSetAttribute(gemm1_kernel, cudaFuncAttributeMaxDynamicSharedMemorySize, 73728);
    cudaFuncSetAttribute(rec_kernel, cudaFuncAttributeMaxDynamicSharedMemorySize, rec_smem);

    detect_kernel<<<1, 256>>>((const unsigned*)done);
    prep_kernel<<<256, 256>>>(done, hidden);
    gemm1_kernel<<<dim3(G3 / 128, (Bb * Tt) / 128), 256, 73728>>>(input, W_ih, b_ih);
    rec_kernel<<<NCTA, 256, rec_smem>>>(W_hh, b_hh, out);
    if (out_size >= Bb * Tt * Hh + Bb * Hh)
        tail_kernel<<<64, 1024>>>(out + (size_t)Bb * Tt * Hh);
}

// round 11
// speedup vs baseline: 3.0937x; 1.2081x over previous
#include <cuda_runtime.h>
#include <cuda_bf16.h>

#define Bb 64
#define Tt 512
#define Ii 1024
#define Hh 1024
#define G3 3072
#define NCTA 128
#define WSTR 1028   // W smem row stride (== 4 mod 32 -> conflict-free frags)

// ---------------- scratch (static device globals; no allocation) ----------------
static __device__ float g_gi[(size_t)Tt * Bb * G3];   // [t][b][3H], b_ih folded in
static __device__ float g_h[2][Bb * Hh];              // ping-pong hidden state
static __device__ float g_dm[Tt * Bb];                // [t][b] mask: done?0:1
static __device__ int   g_kind;                       // 1 = done is 1-byte, 0 = 4-byte
static __device__ unsigned g_bar;                     // grid barrier counter

// ---------------- tf32 mma helpers ----------------
__device__ __forceinline__ unsigned f2tf(float x) {
    unsigned r; asm("cvt.rna.tf32.f32 %0, %1;" : "=r"(r) : "f"(x)); return r;
}
// m16n8k8 row.col f32.tf32.tf32.f32
// A: a0=(m=gid,k=tig) a1=(m=gid+8,k=tig) a2=(m=gid,k=tig+4) a3=(m=gid+8,k=tig+4)
// B: b0=(k=tig,n=gid) b1=(k=tig+4,n=gid)
// C: c0=(gid,tig*2) c1=(gid,tig*2+1) c2=(gid+8,tig*2) c3=(gid+8,tig*2+1)
__device__ __forceinline__ void mma8(float* c, const unsigned* a, const unsigned* b) {
    asm("mma.sync.aligned.m16n8k8.row.col.f32.tf32.tf32.f32 "
        "{%0,%1,%2,%3}, {%4,%5,%6,%7}, {%8,%9}, {%0,%1,%2,%3};"
        : "+f"(c[0]), "+f"(c[1]), "+f"(c[2]), "+f"(c[3])
        : "r"(a[0]), "r"(a[1]), "r"(a[2]), "r"(a[3]), "r"(b[0]), "r"(b[1]));
}

// ---------------- done-dtype detection (graph-safe, device-side) ----------------
__global__ void detect_kernel(const unsigned* __restrict__ w) {
    __shared__ int hif, f32f;
    if (threadIdx.x == 0) { hif = 0; f32f = 0; }
    __syncthreads();
    for (int i = threadIdx.x; i < 8192; i += blockDim.x) {
        unsigned v = w[i];
        if (v == 0x3F800000u) atomicOr(&f32f, 1);
        else if (v & 0xFFFFFF00u) atomicOr(&hif, 1);
    }
    __syncthreads();
    if (threadIdx.x == 0) g_kind = (!f32f && hif) ? 1 : 0;
}

__global__ void prep_kernel(const void* __restrict__ done, const float* __restrict__ hidden) {
    int i = blockIdx.x * blockDim.x + threadIdx.x;
    if (i == 0) g_bar = 0u;
    if (i < Tt * Bb) {
        int t = i / Bb, b = i - t * Bb;
        int src = b * Tt + t;   // done is [B,T]
        bool d;
        if (g_kind == 1) d = ((const unsigned char*)done)[src] != 0;
        else             d = ((const unsigned*)done)[src] != 0u;
        g_dm[i] = d ? 0.f : 1.f;
    }
    if (i < Bb * Hh) g_h[0][i] = hidden[i];
}

// ---------------- GEMM1: gi[t][b][:] = input[b][t][:] @ W_ih^T + b_ih ----------------
__global__ void __launch_bounds__(256) gemm1_kernel(
    const float* __restrict__ A, const float* __restrict__ W,
    const float* __restrict__ bih)
{
    extern __shared__ unsigned sm[];
    unsigned* As = sm;            // [2][128*36]
    unsigned* Bs = sm + 9216;     // [2][128*36]
    const int tid = threadIdx.x;
    const int lane = tid & 31, wid = tid >> 5;
    const int gid = lane >> 2, tig = lane & 3;
    const int wm = (wid >> 2) * 64, wn = (wid & 3) * 32;
    const int n0 = blockIdx.x * 128, m0 = blockIdx.y * 128;  // N fastest -> W_ih L2-resident
    const int r0 = tid >> 3, c4 = tid & 7;

    float c[4][4][4];
    #pragma unroll
    for (int i = 0; i < 4; i++)
        #pragma unroll
        for (int j = 0; j < 4; j++)
            #pragma unroll
            for (int k = 0; k < 4; k++) c[i][j][k] = 0.f;

    #pragma unroll
    for (int i = 0; i < 4; i++) {
        int row = r0 + i * 32;
        float4 va = *(const float4*)&A[(size_t)(m0 + row) * Ii + c4 * 4];
        float4 vb = *(const float4*)&W[(size_t)(n0 + row) * Ii + c4 * 4];
        int ba = row * 36 + c4 * 4;
        As[ba] = f2tf(va.x); As[ba+1] = f2tf(va.y); As[ba+2] = f2tf(va.z); As[ba+3] = f2tf(va.w);
        Bs[ba] = f2tf(vb.x); Bs[ba+1] = f2tf(vb.y); Bs[ba+2] = f2tf(vb.z); Bs[ba+3] = f2tf(vb.w);
    }
    __syncthreads();

    for (int kt = 0; kt < 32; ++kt) {
        const int cur = (kt & 1) * 4608;
        float4 pa[4], pb[4];
        if (kt < 31) {
            int k0 = (kt + 1) * 32;
            #pragma unroll
            for (int i = 0; i < 4; i++) {
                int row = r0 + i * 32;
                pa[i] = *(const float4*)&A[(size_t)(m0 + row) * Ii + k0 + c4 * 4];
                pb[i] = *(const float4*)&W[(size_t)(n0 + row) * Ii + k0 + c4 * 4];
            }
        }
        #pragma unroll
        for (int kk = 0; kk < 32; kk += 8) {
            unsigned a[4][4], b[4][2];
            #pragma unroll
            for (int im = 0; im < 4; im++) {
                int base = cur + (wm + im * 16 + gid) * 36 + kk + tig;
                a[im][0] = As[base];       a[im][1] = As[base + 288];
                a[im][2] = As[base + 4];   a[im][3] = As[base + 292];
            }
            #pragma unroll
            for (int in = 0; in < 4; in++) {
                int base = cur + (wn + in * 8 + gid) * 36 + kk + tig;
                b[in][0] = Bs[base]; b[in][1] = Bs[base + 4];
            }
            #pragma unroll
            for (int im = 0; im < 4; im++)
                #pragma unroll
                for (int in = 0; in < 4; in++)
                    mma8(c[im][in], a[im], b[in]);
        }
        if (kt < 31) {
            const int nxt = ((kt + 1) & 1) * 4608;
            #pragma unroll
            for (int i = 0; i < 4; i++) {
                int row = r0 + i * 32;
                int ba = nxt + row * 36 + c4 * 4;
                As[ba] = f2tf(pa[i].x); As[ba+1] = f2tf(pa[i].y); As[ba+2] = f2tf(pa[i].z); As[ba+3] = f2tf(pa[i].w);
                Bs[ba] = f2tf(pb[i].x); Bs[ba+1] = f2tf(pb[i].y); Bs[ba+2] = f2tf(pb[i].z); Bs[ba+3] = f2tf(pb[i].w);
            }
            __syncthreads();
        }
    }

    #pragma unroll
    for (int im = 0; im < 4; im++) {
        int mA = m0 + wm + im * 16 + gid;
        int mB = mA + 8;
        int rowA = (mA & 511) * Bb + (mA >> 9);
        int rowB = (mB & 511) * Bb + (mB >> 9);
        #pragma unroll
        for (int in = 0; in < 4; in++) {
            int cn = n0 + wn + in * 8 + tig * 2;
            float bx = bih[cn], by = bih[cn + 1];
            float2 v0 = make_float2(c[im][in][0] + bx, c[im][in][1] + by);
            float2 v1 = make_float2(c[im][in][2] + bx, c[im][in][3] + by);
            *(float2*)&g_gi[(size_t)rowA * G3 + cn] = v0;
            *(float2*)&g_gi[(size_t)rowB * G3 + cn] = v1;
        }
    }
}

// ---------------- persistent recurrent kernel: all 512 steps ----------------
// 128 CTAs x 8 h-cols, 256 threads = 8 warps, K-SPLIT (warps 0-3: K[0,512),
// warps 4-7: K[512,1024)). SYNC-FREE MAINLOOP: each warp cp.asyncs its OWN
// 16x32 h slab into a private 4-stage smem ring and consumes it with only
// warp-local cp.async.wait_group — no __syncthreads until the reduction.
// W_hh slice resident in smem (tf32), done-mask applied post-GEMM.
__global__ void __launch_bounds__(256, 1) rec_kernel(
    const float* __restrict__ Whh, const float* __restrict__ bhh,
    float* __restrict__ outp)
{
    extern __shared__ unsigned dyn[];
    unsigned* ws = dyn;                          // 24 * WSTR (tf32)
    unsigned* hsu = dyn + 24 * WSTR;             // 8 warps x 4 stages x 16*36 fp32 bits
    __shared__ float red[128 * 13];              // K-split partials (separate; no alias)
    __shared__ float bsh[24];

    const int tid = threadIdx.x;
    const int lane = tid & 31, wid = tid >> 5;
    const int gid = lane >> 2, tig = lane & 3;
    const int ks = wid >> 2;                     // K-split group 0/1
    const int mrow0 = (wid & 3) * 16;            // warp's 16 M-rows
    const int col0 = blockIdx.x * 8;
    const int b0r = mrow0 + gid;
    unsigned* hw = hsu + wid * 2304;             // this warp's 4-stage ring
    const unsigned hw_u32 = (unsigned)__cvta_generic_to_shared(hw);

    // Load W slice once: row r = (gate r/8, col col0 + r%8), K=1024, tf32.
    for (int f = tid; f < 24 * 256; f += 256) {
        int r = f >> 8, cq = f & 255;
        float4 v = *(const float4*)&Whh[(size_t)((r >> 3) * Hh + col0 + (r & 7)) * Hh + cq * 4];
        int ba = r * WSTR + cq * 4;
        ws[ba]   = f2tf(v.x); ws[ba+1] = f2tf(v.y);
        ws[ba+2] = f2tf(v.z); ws[ba+3] = f2tf(v.w);
    }
    if (tid < 24) bsh[tid] = bhh[(tid >> 3) * Hh + col0 + (tid & 7)];

    // Warps 0-3: this thread's own h entries (fragment layout), in regs across steps.
    float hloc[4] = {0.f, 0.f, 0.f, 0.f};
    if (wid < 4) {
        int cb = col0 + tig * 2;
        hloc[0] = g_h[0][b0r * Hh + cb];
        hloc[1] = g_h[0][b0r * Hh + cb + 1];
        hloc[2] = g_h[0][(b0r + 8) * Hh + cb];
        hloc[3] = g_h[0][(b0r + 8) * Hh + cb + 1];
    }
    __syncthreads();

    const int kbase = ks * 512;                  // warp group's K offset

// warp-local chunk: 16 rows x 32 floats of h (this warp's M rows, its K-half)
#define ISSUE_CHUNK(ch) do {                                                     \
        unsigned _base = hw_u32 + ((unsigned)((((ch) & 3) * 576) << 2));         \
        _Pragma("unroll")                                                        \
        for (int _j = 0; _j < 4; _j++) {                                         \
            int _idx = _j * 32 + lane, _row = _idx >> 3, _cc = _idx & 7;         \
            unsigned _dst = _base + ((unsigned)(_row * 36 + _cc * 4) << 2);      \
            const float* _src = h_in + (mrow0 + _row) * Hh + kbase + (ch) * 32 + _cc * 4; \
            asm volatile("cp.async.cg.shared.global [%0], [%1], 16;"             \
                         :: "r"(_dst), "l"(_src));                               \
        }                                                                        \
        asm volatile("cp.async.commit_group;");                                  \
    } while (0)

    for (int t = 0; t < Tt; ++t) {
        const float* __restrict__ h_in  = g_h[t & 1];
        float* __restrict__       h_out = g_h[(t + 1) & 1];
        const float* __restrict__ gi_t  = g_gi + (size_t)t * (Bb * G3);

        // warps 0-3: prefetch gi + done-mask (independent of h; hides DRAM lat)
        float gpre[12], mb0 = 0.f, mb1 = 0.f;
        if (wid < 4) {
            int cb = col0 + tig * 2;
            const float* g0 = gi_t + (size_t)b0r * G3;
            const float* g1 = gi_t + (size_t)(b0r + 8) * G3;
            #pragma unroll
            for (int g = 0; g < 3; g++) {
                gpre[g * 2]         = __ldcg(g0 + g * Hh + cb);
                gpre[g * 2 + 1]     = __ldcg(g0 + g * Hh + cb + 1);
                gpre[6 + g * 2]     = __ldcg(g1 + g * Hh + cb);
                gpre[6 + g * 2 + 1] = __ldcg(g1 + g * Hh + cb + 1);
            }
            mb0 = __ldg(&g_dm[t * Bb + b0r]);
            mb1 = __ldg(&g_dm[t * Bb + b0r + 8]);
        }

        ISSUE_CHUNK(0); ISSUE_CHUNK(1); ISSUE_CHUNK(2);

        float c[3][4];
        #pragma unroll
        for (int g = 0; g < 3; g++)
            #pragma unroll
            for (int s = 0; s < 4; s++) c[g][s] = 0.f;

        #pragma unroll 1
        for (int i = 0; i < 16; ++i) {
            if (i < 14)       asm volatile("cp.async.wait_group 2;");
            else if (i == 14) asm volatile("cp.async.wait_group 1;");
            else              asm volatile("cp.async.wait_group 0;");
            if (i + 3 < 16) ISSUE_CHUNK(i + 3);

            unsigned* hcur = hw + (i & 3) * 576;
            const int kb = kbase + i * 32;
            #pragma unroll
            for (int kk = 0; kk < 32; kk += 8) {
                unsigned a[4];
                int ab = gid * 36 + kk + tig;
                a[0] = hcur[ab];     a[1] = hcur[ab + 288];
                a[2] = hcur[ab + 4]; a[3] = hcur[ab + 292];
                #pragma unroll
                for (int g = 0; g < 3; g++) {
                    unsigned b[2];
                    int bb = (g * 8 + gid) * WSTR + kb + kk + tig;
                    b[0] = ws[bb]; b[1] = ws[bb + 4];
                    mma8(c[g], a, b);
                }
            }
        }

        // K-split reduction: warps 4-7 park partials, one sync, warps 0-3 finish.
        if (wid >= 4) {
            int base = (tid - 128) * 13;
            #pragma unroll
            for (int g = 0; g < 3; g++)
                #pragma unroll
                for (int s = 0; s < 4; s++) red[base + g * 4 + s] = c[g][s];
        }
        __syncthreads();

        if (wid < 4) {
            int base = tid * 13;
            float hn[4];
            #pragma unroll
            for (int s = 0; s < 4; s++) {
                int r = s >> 1, i = s & 1;
                int cc = tig * 2 + i;
                float mb = r ? mb1 : mb0;
                float gr = (c[0][s] + red[base + s])     * mb + bsh[cc];
                float gz = (c[1][s] + red[base + 4 + s]) * mb + bsh[8 + cc];
                float gn = (c[2][s] + red[base + 8 + s]) * mb + bsh[16 + cc];
                float rg = 1.f / (1.f + __expf(-(gpre[r * 6 + i] + gr)));
                float zg = 1.f / (1.f + __expf(-(gpre[r * 6 + 2 + i] + gz)));
                float ng = tanhf(gpre[r * 6 + 4 + i] + rg * gn);
                float hm = hloc[s] * mb;
                hn[s] = (1.f - zg) * ng + zg * hm;
                hloc[s] = hn[s];
            }
            int cb = col0 + tig * 2;
            __stcg((float2*)&h_out[b0r * Hh + cb],       make_float2(hn[0], hn[1]));
            __stcg((float2*)&h_out[(b0r + 8) * Hh + cb], make_float2(hn[2], hn[3]));
            __stcs((float2*)&outp[((size_t)b0r * Tt + t) * Hh + cb],       make_float2(hn[0], hn[1]));
            __stcs((float2*)&outp[((size_t)(b0r + 8) * Tt + t) * Hh + cb], make_float2(hn[2], hn[3]));
        }

        // grid barrier: release h_out, arrive, spin until all CTAs arrived.
        __threadfence();
        __syncthreads();
        if (tid == 0) {
            atomicAdd(&g_bar, 1u);
            unsigned target = (unsigned)(t + 1) * (unsigned)gridDim.x;
            while (*(volatile unsigned*)&g_bar < target) { }
            __threadfence();
        }
        __syncthreads();
    }
#undef ISSUE_CHUNK
}

__global__ void tail_kernel(float* __restrict__ dst) {
    int i = blockIdx.x * blockDim.x + threadIdx.x;
    if (i < Bb * Hh) dst[i] = g_h[0][i];   // after 512 steps, h_last lives in g_h[0]
}

extern "C" void kernel_launch(void* const* d_in, const int* in_sizes, int n_in,
                              void* d_out, int out_size) {
    const float* input  = (const float*)d_in[0];
    const float* hidden = (const float*)d_in[1];
    const void*  done   = d_in[2];
    const float* W_ih   = (const float*)d_in[3];
    const float* W_hh   = (const float*)d_in[4];
    const float* b_ih   = (const float*)d_in[5];
    const float* b_hh   = (const float*)d_in[6];
    float* out = (float*)d_out;

    const int rec_smem = (24 * WSTR + 8 * 2304) * 4;  // 172416 B dynamic

    cudaFuncSetAttribute(gemm1_kernel, cudaFuncAttributeMaxDynamicSharedMemorySize, 73728);
    cudaFuncSetAttribute(rec_kernel, cudaFuncAttributeMaxDynamicSharedMemorySize, rec_smem);

    detect_kernel<<<1, 256>>>((const unsigned*)done);
    prep_kernel<<<256, 256>>>(done, hidden);
    gemm1_kernel<<<dim3(G3 / 128, (Bb * Tt) / 128), 256, 73728>>>(input, W_ih, b_ih);
    rec_kernel<<<NCTA, 256, rec_smem>>>(W_hh, b_hh, out);
    if (out_size >= Bb * Tt * Hh + Bb * Hh)
        tail_kernel<<<64, 1024>>>(out + (size_t)Bb * Tt * Hh);
}

// round 12
// speedup vs baseline: 3.4712x; 1.1220x over previous
#include <cuda_runtime.h>
#include <cuda_bf16.h>

#define Bb 64
#define Tt 512
#define Ii 1024
#define Hh 1024
#define G3 3072
#define NCTA 128
#define WSTR 1028   // W smem row stride (== 4 mod 32 -> conflict-free frags)

// ---------------- scratch (static device globals; no allocation) ----------------
static __device__ float g_gi[(size_t)Tt * Bb * G3];   // [t][b][3H], b_ih folded in
static __device__ float g_h[2][Bb * Hh];              // ping-pong hidden state
static __device__ float g_dm[Tt * Bb];                // [t][b] mask: done?0:1
static __device__ int   g_kind;                       // 1 = done is 1-byte, 0 = 4-byte
static __device__ unsigned g_bar;                     // grid barrier counter

// ---------------- tf32 mma helpers ----------------
__device__ __forceinline__ unsigned f2tf(float x) {
    unsigned r; asm("cvt.rna.tf32.f32 %0, %1;" : "=r"(r) : "f"(x)); return r;
}
// m16n8k8 row.col f32.tf32.tf32.f32
// A: a0=(m=gid,k=tig) a1=(m=gid+8,k=tig) a2=(m=gid,k=tig+4) a3=(m=gid+8,k=tig+4)
// B: b0=(k=tig,n=gid) b1=(k=tig+4,n=gid)
// C: c0=(gid,tig*2) c1=(gid,tig*2+1) c2=(gid+8,tig*2) c3=(gid+8,tig*2+1)
__device__ __forceinline__ void mma8(float* c, const unsigned* a, const unsigned* b) {
    asm("mma.sync.aligned.m16n8k8.row.col.f32.tf32.tf32.f32 "
        "{%0,%1,%2,%3}, {%4,%5,%6,%7}, {%8,%9}, {%0,%1,%2,%3};"
        : "+f"(c[0]), "+f"(c[1]), "+f"(c[2]), "+f"(c[3])
        : "r"(a[0]), "r"(a[1]), "r"(a[2]), "r"(a[3]), "r"(b[0]), "r"(b[1]));
}
// ldmatrix x4: 4 8x8 b16 tiles == 4 tf32 8x4 quads; lane reg = one aligned tf32
#define LDSM4(r, addr)                                                            \
    asm volatile("ldmatrix.sync.aligned.m8n8.x4.shared.b16 {%0,%1,%2,%3}, [%4];"  \
                 : "=r"((r)[0]), "=r"((r)[1]), "=r"((r)[2]), "=r"((r)[3])         \
                 : "r"(addr))

// ---------------- done-dtype detection (graph-safe, device-side) ----------------
__global__ void detect_kernel(const unsigned* __restrict__ w) {
    __shared__ int hif, f32f;
    if (threadIdx.x == 0) { hif = 0; f32f = 0; }
    __syncthreads();
    for (int i = threadIdx.x; i < 8192; i += blockDim.x) {
        unsigned v = w[i];
        if (v == 0x3F800000u) atomicOr(&f32f, 1);
        else if (v & 0xFFFFFF00u) atomicOr(&hif, 1);
    }
    __syncthreads();
    if (threadIdx.x == 0) g_kind = (!f32f && hif) ? 1 : 0;
}

__global__ void prep_kernel(const void* __restrict__ done, const float* __restrict__ hidden) {
    int i = blockIdx.x * blockDim.x + threadIdx.x;
    if (i == 0) g_bar = 0u;
    if (i < Tt * Bb) {
        int t = i / Bb, b = i - t * Bb;
        int src = b * Tt + t;   // done is [B,T]
        bool d;
        if (g_kind == 1) d = ((const unsigned char*)done)[src] != 0;
        else             d = ((const unsigned*)done)[src] != 0u;
        g_dm[i] = d ? 0.f : 1.f;
    }
    if (i < Bb * Hh) g_h[0][i] = hidden[i];
}

// ---------------- GEMM1: gi[t][b][:] = input[b][t][:] @ W_ih^T + b_ih ----------------
__global__ void __launch_bounds__(256) gemm1_kernel(
    const float* __restrict__ A, const float* __restrict__ W,
    const float* __restrict__ bih)
{
    extern __shared__ unsigned sm[];
    unsigned* As = sm;            // [2][128*36]
    unsigned* Bs = sm + 9216;     // [2][128*36]
    const int tid = threadIdx.x;
    const int lane = tid & 31, wid = tid >> 5;
    const int gid = lane >> 2, tig = lane & 3;
    const int wm = (wid >> 2) * 64, wn = (wid & 3) * 32;
    const int n0 = blockIdx.x * 128, m0 = blockIdx.y * 128;  // N fastest -> W_ih L2-resident
    const int r0 = tid >> 3, c4 = tid & 7;

    float c[4][4][4];
    #pragma unroll
    for (int i = 0; i < 4; i++)
        #pragma unroll
        for (int j = 0; j < 4; j++)
            #pragma unroll
            for (int k = 0; k < 4; k++) c[i][j][k] = 0.f;

    #pragma unroll
    for (int i = 0; i < 4; i++) {
        int row = r0 + i * 32;
        float4 va = *(const float4*)&A[(size_t)(m0 + row) * Ii + c4 * 4];
        float4 vb = *(const float4*)&W[(size_t)(n0 + row) * Ii + c4 * 4];
        int ba = row * 36 + c4 * 4;
        As[ba] = f2tf(va.x); As[ba+1] = f2tf(va.y); As[ba+2] = f2tf(va.z); As[ba+3] = f2tf(va.w);
        Bs[ba] = f2tf(vb.x); Bs[ba+1] = f2tf(vb.y); Bs[ba+2] = f2tf(vb.z); Bs[ba+3] = f2tf(vb.w);
    }
    __syncthreads();

    for (int kt = 0; kt < 32; ++kt) {
        const int cur = (kt & 1) * 4608;
        float4 pa[4], pb[4];
        if (kt < 31) {
            int k0 = (kt + 1) * 32;
            #pragma unroll
            for (int i = 0; i < 4; i++) {
                int row = r0 + i * 32;
                pa[i] = *(const float4*)&A[(size_t)(m0 + row) * Ii + k0 + c4 * 4];
                pb[i] = *(const float4*)&W[(size_t)(n0 + row) * Ii + k0 + c4 * 4];
            }
        }
        #pragma unroll
        for (int kk = 0; kk < 32; kk += 8) {
            unsigned a[4][4], b[4][2];
            #pragma unroll
            for (int im = 0; im < 4; im++) {
                int base = cur + (wm + im * 16 + gid) * 36 + kk + tig;
                a[im][0] = As[base];       a[im][1] = As[base + 288];
                a[im][2] = As[base + 4];   a[im][3] = As[base + 292];
            }
            #pragma unroll
            for (int in = 0; in < 4; in++) {
                int base = cur + (wn + in * 8 + gid) * 36 + kk + tig;
                b[in][0] = Bs[base]; b[in][1] = Bs[base + 4];
            }
            #pragma unroll
            for (int im = 0; im < 4; im++)
                #pragma unroll
                for (int in = 0; in < 4; in++)
                    mma8(c[im][in], a[im], b[in]);
        }
        if (kt < 31) {
            const int nxt = ((kt + 1) & 1) * 4608;
            #pragma unroll
            for (int i = 0; i < 4; i++) {
                int row = r0 + i * 32;
                int ba = nxt + row * 36 + c4 * 4;
                As[ba] = f2tf(pa[i].x); As[ba+1] = f2tf(pa[i].y); As[ba+2] = f2tf(pa[i].z); As[ba+3] = f2tf(pa[i].w);
                Bs[ba] = f2tf(pb[i].x); Bs[ba+1] = f2tf(pb[i].y); Bs[ba+2] = f2tf(pb[i].z); Bs[ba+3] = f2tf(pb[i].w);
            }
            __syncthreads();
        }
    }

    #pragma unroll
    for (int im = 0; im < 4; im++) {
        int mA = m0 + wm + im * 16 + gid;
        int mB = mA + 8;
        int rowA = (mA & 511) * Bb + (mA >> 9);
        int rowB = (mB & 511) * Bb + (mB >> 9);
        #pragma unroll
        for (int in = 0; in < 4; in++) {
            int cn = n0 + wn + in * 8 + tig * 2;
            float bx = bih[cn], by = bih[cn + 1];
            float2 v0 = make_float2(c[im][in][0] + bx, c[im][in][1] + by);
            float2 v1 = make_float2(c[im][in][2] + bx, c[im][in][3] + by);
            *(float2*)&g_gi[(size_t)rowA * G3 + cn] = v0;
            *(float2*)&g_gi[(size_t)rowB * G3 + cn] = v1;
        }
    }
}

// ---------------- persistent recurrent kernel: all 512 steps ----------------
// 128 CTAs x 8 h-cols, 256 threads = 8 warps, K-SPLIT (warps 0-3: K[0,512),
// warps 4-7: K[512,1024)). Sync-free mainloop with warp-private 4-stage
// cp.async rings. Fragment loads via ldmatrix.x4 (10 LDSM per 32-K chunk
// instead of 40 LDS.32). Lightweight release/acquire grid barrier per step.
__global__ void __launch_bounds__(256, 1) rec_kernel(
    const float* __restrict__ Whh, const float* __restrict__ bhh,
    float* __restrict__ outp)
{
    extern __shared__ unsigned dyn[];
    unsigned* ws = dyn;                          // 24 * WSTR (tf32)
    unsigned* hsu = dyn + 24 * WSTR;             // 8 warps x 4 stages x 16*36 fp32 bits
    __shared__ float red[128 * 13];              // K-split partials (separate; no alias)
    __shared__ float bsh[24];

    const int tid = threadIdx.x;
    const int lane = tid & 31, wid = tid >> 5;
    const int gid = lane >> 2, tig = lane & 3;
    const int ks = wid >> 2;                     // K-split group 0/1
    const int mrow0 = (wid & 3) * 16;            // warp's 16 M-rows
    const int col0 = blockIdx.x * 8;
    const int b0r = mrow0 + gid;
    unsigned* hw = hsu + wid * 2304;             // this warp's 4-stage ring
    const unsigned hw_u32 = (unsigned)__cvta_generic_to_shared(hw);
    const unsigned ws_u32 = (unsigned)__cvta_generic_to_shared(ws);

    // Load W slice once: row r = (gate r/8, col col0 + r%8), K=1024, tf32.
    for (int f = tid; f < 24 * 256; f += 256) {
        int r = f >> 8, cq = f & 255;
        float4 v = *(const float4*)&Whh[(size_t)((r >> 3) * Hh + col0 + (r & 7)) * Hh + cq * 4];
        int ba = r * WSTR + cq * 4;
        ws[ba]   = f2tf(v.x); ws[ba+1] = f2tf(v.y);
        ws[ba+2] = f2tf(v.z); ws[ba+3] = f2tf(v.w);
    }
    if (tid < 24) bsh[tid] = bhh[(tid >> 3) * Hh + col0 + (tid & 7)];

    // ldmatrix per-lane addressing.
    // A tiles: t0 rows0-7/k0-3, t1 rows8-15/k0-3, t2 rows0-7/k4-7, t3 rows8-15/k4-7
    const int arow = (lane < 16) ? lane : (lane - 16);
    const int akoff = (lane >= 16) ? 4 : 0;
    const unsigned a_addr0 = hw_u32 + ((unsigned)(arow * 36 + akoff) << 2);
    // B tiles (per gate): t = lane>>3 selects k quad (t*4), row = lane&7 (n)
    const int b_nrow = lane & 7, b_k4 = (lane >> 3) * 4;
    unsigned b_addr[3];
    #pragma unroll
    for (int g = 0; g < 3; g++)
        b_addr[g] = ws_u32 + ((unsigned)((g * 8 + b_nrow) * WSTR + b_k4) << 2);

    // Warps 0-3: this thread's own h entries (fragment layout), in regs across steps.
    float hloc[4] = {0.f, 0.f, 0.f, 0.f};
    if (wid < 4) {
        int cb = col0 + tig * 2;
        hloc[0] = g_h[0][b0r * Hh + cb];
        hloc[1] = g_h[0][b0r * Hh + cb + 1];
        hloc[2] = g_h[0][(b0r + 8) * Hh + cb];
        hloc[3] = g_h[0][(b0r + 8) * Hh + cb + 1];
    }
    __syncthreads();

    const int kbase = ks * 512;                  // warp group's K offset (words)

// warp-local chunk: 16 rows x 32 floats of h (this warp's M rows, its K-half)
#define ISSUE_CHUNK(ch) do {                                                     \
        unsigned _base = hw_u32 + ((unsigned)((((ch) & 3) * 576) << 2));         \
        _Pragma("unroll")                                                        \
        for (int _j = 0; _j < 4; _j++) {                                         \
            int _idx = _j * 32 + lane, _row = _idx >> 3, _cc = _idx & 7;         \
            unsigned _dst = _base + ((unsigned)(_row * 36 + _cc * 4) << 2);      \
            const float* _src = h_in + (mrow0 + _row) * Hh + kbase + (ch) * 32 + _cc * 4; \
            asm volatile("cp.async.cg.shared.global [%0], [%1], 16;"             \
                         :: "r"(_dst), "l"(_src));                               \
        }                                                                        \
        asm volatile("cp.async.commit_group;");                                  \
    } while (0)

    for (int t = 0; t < Tt; ++t) {
        const float* __restrict__ h_in  = g_h[t & 1];
        float* __restrict__       h_out = g_h[(t + 1) & 1];
        const float* __restrict__ gi_t  = g_gi + (size_t)t * (Bb * G3);

        // warps 0-3: prefetch gi + done-mask (independent of h; hides DRAM lat)
        float gpre[12], mb0 = 0.f, mb1 = 0.f;
        if (wid < 4) {
            int cb = col0 + tig * 2;
            const float* g0 = gi_t + (size_t)b0r * G3;
            const float* g1 = gi_t + (size_t)(b0r + 8) * G3;
            #pragma unroll
            for (int g = 0; g < 3; g++) {
                float2 p0 = __ldcg((const float2*)(g0 + g * Hh + cb));
                float2 p1 = __ldcg((const float2*)(g1 + g * Hh + cb));
                gpre[g * 2] = p0.x;     gpre[g * 2 + 1] = p0.y;
                gpre[6 + g * 2] = p1.x; gpre[6 + g * 2 + 1] = p1.y;
            }
            mb0 = __ldg(&g_dm[t * Bb + b0r]);
            mb1 = __ldg(&g_dm[t * Bb + b0r + 8]);
        }

        ISSUE_CHUNK(0); ISSUE_CHUNK(1); ISSUE_CHUNK(2);

        float c[3][4];
        #pragma unroll
        for (int g = 0; g < 3; g++)
            #pragma unroll
            for (int s = 0; s < 4; s++) c[g][s] = 0.f;

        #pragma unroll 1
        for (int i = 0; i < 16; ++i) {
            if (i < 14)       asm volatile("cp.async.wait_group 2;");
            else if (i == 14) asm volatile("cp.async.wait_group 1;");
            else              asm volatile("cp.async.wait_group 0;");
            if (i + 3 < 16) ISSUE_CHUNK(i + 3);

            const int kb = kbase + i * 32;
            // B fragments: 2 LDSM.x4 per gate cover all 4 kk quads
            unsigned bf[3][8];
            #pragma unroll
            for (int g = 0; g < 3; g++) {
                LDSM4(&bf[g][0], b_addr[g] + ((unsigned)kb << 2));
                LDSM4(&bf[g][4], b_addr[g] + ((unsigned)(kb + 16) << 2));
            }
            const unsigned stg = (unsigned)((i & 3) * 576) << 2;
            #pragma unroll
            for (int kq = 0; kq < 4; kq++) {     // kk = kq*8
                unsigned a[4];
                LDSM4(a, a_addr0 + stg + ((unsigned)(kq * 8) << 2));
                #pragma unroll
                for (int g = 0; g < 3; g++)
                    mma8(c[g], a, &bf[g][kq * 2]);
            }
        }

        // K-split reduction: warps 4-7 park partials, one sync, warps 0-3 finish.
        if (wid >= 4) {
            int base = (tid - 128) * 13;
            #pragma unroll
            for (int g = 0; g < 3; g++)
                #pragma unroll
                for (int s = 0; s < 4; s++) red[base + g * 4 + s] = c[g][s];
        }
        __syncthreads();

        if (wid < 4) {
            int base = tid * 13;
            float hn[4];
            #pragma unroll
            for (int s = 0; s < 4; s++) {
                int r = s >> 1, i = s & 1;
                int cc = tig * 2 + i;
                float mb = r ? mb1 : mb0;
                float gr = (c[0][s] + red[base + s])     * mb + bsh[cc];
                float gz = (c[1][s] + red[base + 4 + s]) * mb + bsh[8 + cc];
                float gn = (c[2][s] + red[base + 8 + s]) * mb + bsh[16 + cc];
                float rg = 1.f / (1.f + __expf(-(gpre[r * 6 + i] + gr)));
                float zg = 1.f / (1.f + __expf(-(gpre[r * 6 + 2 + i] + gz)));
                float ng = tanhf(gpre[r * 6 + 4 + i] + rg * gn);
                float hm = hloc[s] * mb;
                hn[s] = (1.f - zg) * ng + zg * hm;
                hloc[s] = hn[s];
            }
            int cb = col0 + tig * 2;
            __stcg((float2*)&h_out[b0r * Hh + cb],       make_float2(hn[0], hn[1]));
            __stcg((float2*)&h_out[(b0r + 8) * Hh + cb], make_float2(hn[2], hn[3]));
            __stcs((float2*)&outp[((size_t)b0r * Tt + t) * Hh + cb],       make_float2(hn[0], hn[1]));
            __stcs((float2*)&outp[((size_t)(b0r + 8) * Tt + t) * Hh + cb], make_float2(hn[2], hn[3]));
        }

        // grid barrier: release/acquire (no MEMBAR.GPU). syncthreads->release
        // ->acquire->syncthreads carries the happens-before for h_out.
        __syncthreads();
        if (tid == 0) {
            unsigned target = (unsigned)(t + 1) * (unsigned)gridDim.x;
            unsigned one = 1u, v;
            asm volatile("red.release.gpu.global.add.u32 [%0], %1;"
                         :: "l"(&g_bar), "r"(one) : "memory");
            do {
                asm volatile("ld.acquire.gpu.global.u32 %0, [%1];"
                             : "=r"(v) : "l"(&g_bar) : "memory");
            } while (v < target);
        }
        __syncthreads();
    }
#undef ISSUE_CHUNK
}

__global__ void tail_kernel(float* __restrict__ dst) {
    int i = blockIdx.x * blockDim.x + threadIdx.x;
    if (i < Bb * Hh) dst[i] = g_h[0][i];   // after 512 steps, h_last lives in g_h[0]
}

extern "C" void kernel_launch(void* const* d_in, const int* in_sizes, int n_in,
                              void* d_out, int out_size) {
    const float* input  = (const float*)d_in[0];
    const float* hidden = (const float*)d_in[1];
    const void*  done   = d_in[2];
    const float* W_ih   = (const float*)d_in[3];
    const float* W_hh   = (const float*)d_in[4];
    const float* b_ih   = (const float*)d_in[5];
    const float* b_hh   = (const float*)d_in[6];
    float* out = (float*)d_out;

    const int rec_smem = (24 * WSTR + 8 * 2304) * 4;  // 172416 B dynamic

    cudaFuncSetAttribute(gemm1_kernel, cudaFuncAttributeMaxDynamicSharedMemorySize, 73728);
    cudaFuncSetAttribute(rec_kernel, cudaFuncAttributeMaxDynamicSharedMemorySize, rec_smem);

    detect_kernel<<<1, 256>>>((const unsigned*)done);
    prep_kernel<<<256, 256>>>(done, hidden);
    gemm1_kernel<<<dim3(G3 / 128, (Bb * Tt) / 128), 256, 73728>>>(input, W_ih, b_ih);
    rec_kernel<<<NCTA, 256, rec_smem>>>(W_hh, b_hh, out);
    if (out_size >= Bb * Tt * Hh + Bb * Hh)
        tail_kernel<<<64, 1024>>>(out + (size_t)Bb * Tt * Hh);
}

// round 13
// speedup vs baseline: 3.9158x; 1.1281x over previous
#include <cuda_runtime.h>
#include <cuda_fp16.h>

#define Bb 64
#define Tt 512
#define Ii 1024
#define Hh 1024
#define G3 3072
#define NCTA 128
#define WSTR 1028    // gemm1 W smem row stride (words)
#define WSTRH 1032   // rec W smem row stride (halfs): 2064B == 16 mod 128, 16B-aligned

// ---------------- scratch (static device globals; no allocation) ----------------
static __device__ float g_gi[(size_t)Tt * Bb * G3];   // [t][b][3H], b_ih folded in
static __device__ float g_h[2][Bb * Hh];              // fp32 h (init + final only)
static __device__ __half g_hh[2][Bb * Hh];            // fp16 ping-pong hidden state
static __device__ float g_dm[Tt * Bb];                // [t][b] mask: done?0:1
static __device__ int   g_kind;                       // 1 = done is 1-byte, 0 = 4-byte
static __device__ unsigned g_bar;                     // grid barrier counter

// ---------------- mma helpers ----------------
__device__ __forceinline__ unsigned f2tf(float x) {
    unsigned r; asm("cvt.rna.tf32.f32 %0, %1;" : "=r"(r) : "f"(x)); return r;
}
__device__ __forceinline__ void mma8(float* c, const unsigned* a, const unsigned* b) {
    asm("mma.sync.aligned.m16n8k8.row.col.f32.tf32.tf32.f32 "
        "{%0,%1,%2,%3}, {%4,%5,%6,%7}, {%8,%9}, {%0,%1,%2,%3};"
        : "+f"(c[0]), "+f"(c[1]), "+f"(c[2]), "+f"(c[3])
        : "r"(a[0]), "r"(a[1]), "r"(a[2]), "r"(a[3]), "r"(b[0]), "r"(b[1]));
}
// fp16 m16n8k16: A 4 regs (2 f16 each), B 2 regs, C 4 f32
__device__ __forceinline__ void mma16(float* c, const unsigned* a, const unsigned* b) {
    asm("mma.sync.aligned.m16n8k16.row.col.f32.f16.f16.f32 "
        "{%0,%1,%2,%3}, {%4,%5,%6,%7}, {%8,%9}, {%0,%1,%2,%3};"
        : "+f"(c[0]), "+f"(c[1]), "+f"(c[2]), "+f"(c[3])
        : "r"(a[0]), "r"(a[1]), "r"(a[2]), "r"(a[3]), "r"(b[0]), "r"(b[1]));
}
#define LDSM4(r, addr)                                                            \
    asm volatile("ldmatrix.sync.aligned.m8n8.x4.shared.b16 {%0,%1,%2,%3}, [%4];"  \
                 : "=r"((r)[0]), "=r"((r)[1]), "=r"((r)[2]), "=r"((r)[3])         \
                 : "r"(addr))

// ---------------- done-dtype detection (graph-safe, device-side) ----------------
__global__ void detect_kernel(const unsigned* __restrict__ w) {
    __shared__ int hif, f32f;
    if (threadIdx.x == 0) { hif = 0; f32f = 0; }
    __syncthreads();
    for (int i = threadIdx.x; i < 8192; i += blockDim.x) {
        unsigned v = w[i];
        if (v == 0x3F800000u) atomicOr(&f32f, 1);
        else if (v & 0xFFFFFF00u) atomicOr(&hif, 1);
    }
    __syncthreads();
    if (threadIdx.x == 0) g_kind = (!f32f && hif) ? 1 : 0;
}

__global__ void prep_kernel(const void* __restrict__ done, const float* __restrict__ hidden) {
    int i = blockIdx.x * blockDim.x + threadIdx.x;
    if (i == 0) g_bar = 0u;
    if (i < Tt * Bb) {
        int t = i / Bb, b = i - t * Bb;
        int src = b * Tt + t;   // done is [B,T]
        bool d;
        if (g_kind == 1) d = ((const unsigned char*)done)[src] != 0;
        else             d = ((const unsigned*)done)[src] != 0u;
        g_dm[i] = d ? 0.f : 1.f;
    }
    if (i < Bb * Hh) {
        float hv = hidden[i];
        g_h[0][i] = hv;
        g_hh[0][i] = __float2half_rn(hv);
    }
}

// ---------------- GEMM1: gi[t][b][:] = input[b][t][:] @ W_ih^T + b_ih ----------------
__global__ void __launch_bounds__(256) gemm1_kernel(
    const float* __restrict__ A, const float* __restrict__ W,
    const float* __restrict__ bih)
{
    extern __shared__ unsigned sm[];
    unsigned* As = sm;            // [2][128*36]
    unsigned* Bs = sm + 9216;     // [2][128*36]
    const int tid = threadIdx.x;
    const int lane = tid & 31, wid = tid >> 5;
    const int gid = lane >> 2, tig = lane & 3;
    const int wm = (wid >> 2) * 64, wn = (wid & 3) * 32;
    const int n0 = blockIdx.x * 128, m0 = blockIdx.y * 128;  // N fastest -> W_ih L2-resident
    const int r0 = tid >> 3, c4 = tid & 7;

    float c[4][4][4];
    #pragma unroll
    for (int i = 0; i < 4; i++)
        #pragma unroll
        for (int j = 0; j < 4; j++)
            #pragma unroll
            for (int k = 0; k < 4; k++) c[i][j][k] = 0.f;

    #pragma unroll
    for (int i = 0; i < 4; i++) {
        int row = r0 + i * 32;
        float4 va = *(const float4*)&A[(size_t)(m0 + row) * Ii + c4 * 4];
        float4 vb = *(const float4*)&W[(size_t)(n0 + row) * Ii + c4 * 4];
        int ba = row * 36 + c4 * 4;
        As[ba] = f2tf(va.x); As[ba+1] = f2tf(va.y); As[ba+2] = f2tf(va.z); As[ba+3] = f2tf(va.w);
        Bs[ba] = f2tf(vb.x); Bs[ba+1] = f2tf(vb.y); Bs[ba+2] = f2tf(vb.z); Bs[ba+3] = f2tf(vb.w);
    }
    __syncthreads();

    for (int kt = 0; kt < 32; ++kt) {
        const int cur = (kt & 1) * 4608;
        float4 pa[4], pb[4];
        if (kt < 31) {
            int k0 = (kt + 1) * 32;
            #pragma unroll
            for (int i = 0; i < 4; i++) {
                int row = r0 + i * 32;
                pa[i] = *(const float4*)&A[(size_t)(m0 + row) * Ii + k0 + c4 * 4];
                pb[i] = *(const float4*)&W[(size_t)(n0 + row) * Ii + k0 + c4 * 4];
            }
        }
        #pragma unroll
        for (int kk = 0; kk < 32; kk += 8) {
            unsigned a[4][4], b[4][2];
            #pragma unroll
            for (int im = 0; im < 4; im++) {
                int base = cur + (wm + im * 16 + gid) * 36 + kk + tig;
                a[im][0] = As[base];       a[im][1] = As[base + 288];
                a[im][2] = As[base + 4];   a[im][3] = As[base + 292];
            }
            #pragma unroll
            for (int in = 0; in < 4; in++) {
                int base = cur + (wn + in * 8 + gid) * 36 + kk + tig;
                b[in][0] = Bs[base]; b[in][1] = Bs[base + 4];
            }
            #pragma unroll
            for (int im = 0; im < 4; im++)
                #pragma unroll
                for (int in = 0; in < 4; in++)
                    mma8(c[im][in], a[im], b[in]);
        }
        if (kt < 31) {
            const int nxt = ((kt + 1) & 1) * 4608;
            #pragma unroll
            for (int i = 0; i < 4; i++) {
                int row = r0 + i * 32;
                int ba = nxt + row * 36 + c4 * 4;
                As[ba] = f2tf(pa[i].x); As[ba+1] = f2tf(pa[i].y); As[ba+2] = f2tf(pa[i].z); As[ba+3] = f2tf(pa[i].w);
                Bs[ba] = f2tf(pb[i].x); Bs[ba+1] = f2tf(pb[i].y); Bs[ba+2] = f2tf(pb[i].z); Bs[ba+3] = f2tf(pb[i].w);
            }
            __syncthreads();
        }
    }

    #pragma unroll
    for (int im = 0; im < 4; im++) {
        int mA = m0 + wm + im * 16 + gid;
        int mB = mA + 8;
        int rowA = (mA & 511) * Bb + (mA >> 9);
        int rowB = (mB & 511) * Bb + (mB >> 9);
        #pragma unroll
        for (int in = 0; in < 4; in++) {
            int cn = n0 + wn + in * 8 + tig * 2;
            float bx = bih[cn], by = bih[cn + 1];
            float2 v0 = make_float2(c[im][in][0] + bx, c[im][in][1] + by);
            float2 v1 = make_float2(c[im][in][2] + bx, c[im][in][3] + by);
            *(float2*)&g_gi[(size_t)rowA * G3 + cn] = v0;
            *(float2*)&g_gi[(size_t)rowB * G3 + cn] = v1;
        }
    }
}

// ---------------- persistent recurrent kernel: all 512 steps, fp16 MMA ----------------
// 128 CTAs x 8 h-cols, 8 warps, K-split (warps 0-3: K[0,512), 4-7: K[512,1024)).
// Sync-free mainloop: warp-private 4-stage cp.async rings of fp16 h (halved L2
// traffic). W_hh resident in smem as fp16. m16n8k16 HMMA: per 32-K chunk only
// 5 LDSM.x4 + 6 MMA. fp32 accumulate + fp32 gate math. Release/acquire barrier.
__global__ void __launch_bounds__(256, 1) rec_kernel(
    const float* __restrict__ Whh, const float* __restrict__ bhh,
    float* __restrict__ outp)
{
    extern __shared__ unsigned dyn[];
    __half* wsh = (__half*)dyn;                  // 24 * WSTRH halfs (49536 B)
    __half* hsu = wsh + 24 * WSTRH;              // 8 warps x 4 stages x 16*40 halfs (40960 B)
    __shared__ float red[128 * 13];              // K-split partials
    __shared__ float bsh[24];

    const int tid = threadIdx.x;
    const int lane = tid & 31, wid = tid >> 5;
    const int gid = lane >> 2, tig = lane & 3;
    const int ks = wid >> 2;                     // K-split group 0/1
    const int mrow0 = (wid & 3) * 16;            // warp's 16 M-rows
    const int col0 = blockIdx.x * 8;
    const int b0r = mrow0 + gid;
    __half* hw = hsu + wid * 2560;               // this warp's 4-stage ring (5120 B)
    const unsigned hw_u32 = (unsigned)__cvta_generic_to_shared(hw);
    const unsigned ws_u32 = (unsigned)__cvta_generic_to_shared(wsh);

    // Load W slice once (fp16): row r = (gate r/8, col col0 + r%8), K=1024.
    for (int f = tid; f < 24 * 256; f += 256) {
        int r = f >> 8, cq = f & 255;
        float4 v = *(const float4*)&Whh[(size_t)((r >> 3) * Hh + col0 + (r & 7)) * Hh + cq * 4];
        __half2 h0 = __floats2half2_rn(v.x, v.y);
        __half2 h1 = __floats2half2_rn(v.z, v.w);
        *(__half2*)&wsh[r * WSTRH + cq * 4]     = h0;
        *(__half2*)&wsh[r * WSTRH + cq * 4 + 2] = h1;
    }
    if (tid < 24) bsh[tid] = bhh[(tid >> 3) * Hh + col0 + (tid & 7)];

    // ldmatrix per-lane addressing.
    // A (16x16 f16): t0 rows0-7/k0-7, t1 rows8-15/k0-7, t2 rows0-7/k8-15, t3 rows8-15/k8-15
    const int arow = (lane < 16) ? lane : (lane - 16);
    const int akoff = (lane >= 16) ? 8 : 0;                      // halfs
    const unsigned a_addr0 = hw_u32 + ((unsigned)(arow * 40 + akoff) << 1);
    // B (per gate, 4 tiles cover k..k+31): row = lane&7 (n), k-offset = (lane>>3)*8 halfs
    const int b_nrow = lane & 7, b_k8 = (lane >> 3) * 8;
    unsigned b_addr[3];
    #pragma unroll
    for (int g = 0; g < 3; g++)
        b_addr[g] = ws_u32 + ((unsigned)((g * 8 + b_nrow) * WSTRH + b_k8) << 1);

    // Warps 0-3: own h entries (fragment layout) live in regs across steps.
    float hloc[4] = {0.f, 0.f, 0.f, 0.f};
    if (wid < 4) {
        int cb = col0 + tig * 2;
        hloc[0] = g_h[0][b0r * Hh + cb];
        hloc[1] = g_h[0][b0r * Hh + cb + 1];
        hloc[2] = g_h[0][(b0r + 8) * Hh + cb];
        hloc[3] = g_h[0][(b0r + 8) * Hh + cb + 1];
    }
    __syncthreads();

    const int kbase = ks * 512;                  // warp group's K offset (halfs)

// warp-local chunk: 16 rows x 32 halfs; 2 cp.async (16B) per lane
#define ISSUE_CHUNK(ch) do {                                                     \
        unsigned _base = hw_u32 + (unsigned)((((ch) & 3) * 1280));               \
        _Pragma("unroll")                                                        \
        for (int _j = 0; _j < 2; _j++) {                                         \
            int _idx = _j * 32 + lane, _row = _idx >> 2, _seg = _idx & 3;        \
            unsigned _dst = _base + (unsigned)(_row * 80 + _seg * 16);           \
            const __half* _src = hh_in + (mrow0 + _row) * Hh + kbase + (ch) * 32 + _seg * 8; \
            asm volatile("cp.async.cg.shared.global [%0], [%1], 16;"             \
                         :: "r"(_dst), "l"(_src));                               \
        }                                                                        \
        asm volatile("cp.async.commit_group;");                                  \
    } while (0)

    for (int t = 0; t < Tt; ++t) {
        const __half* __restrict__ hh_in  = g_hh[t & 1];
        __half* __restrict__       hh_out = g_hh[(t + 1) & 1];
        const float* __restrict__  gi_t   = g_gi + (size_t)t * (Bb * G3);

        // warps 0-3: prefetch gi + done-mask (independent of h; hides DRAM lat)
        float gpre[12], mb0 = 0.f, mb1 = 0.f;
        if (wid < 4) {
            int cb = col0 + tig * 2;
            const float* g0 = gi_t + (size_t)b0r * G3;
            const float* g1 = gi_t + (size_t)(b0r + 8) * G3;
            #pragma unroll
            for (int g = 0; g < 3; g++) {
                float2 p0 = __ldcg((const float2*)(g0 + g * Hh + cb));
                float2 p1 = __ldcg((const float2*)(g1 + g * Hh + cb));
                gpre[g * 2] = p0.x;     gpre[g * 2 + 1] = p0.y;
                gpre[6 + g * 2] = p1.x; gpre[6 + g * 2 + 1] = p1.y;
            }
            mb0 = __ldg(&g_dm[t * Bb + b0r]);
            mb1 = __ldg(&g_dm[t * Bb + b0r + 8]);
        }

        ISSUE_CHUNK(0); ISSUE_CHUNK(1); ISSUE_CHUNK(2);

        float c[3][4];
        #pragma unroll
        for (int g = 0; g < 3; g++)
            #pragma unroll
            for (int s = 0; s < 4; s++) c[g][s] = 0.f;

        #pragma unroll 1
        for (int i = 0; i < 16; ++i) {
            if (i < 14)       asm volatile("cp.async.wait_group 2;");
            else if (i == 14) asm volatile("cp.async.wait_group 1;");
            else              asm volatile("cp.async.wait_group 0;");
            if (i + 3 < 16) ISSUE_CHUNK(i + 3);

            const int kb = kbase + i * 32;       // halfs
            // B fragments: one LDSM.x4 per gate covers k..k+31
            unsigned bf[3][4];
            #pragma unroll
            for (int g = 0; g < 3; g++)
                LDSM4(bf[g], b_addr[g] + ((unsigned)kb << 1));
            const unsigned stg = (unsigned)((i & 3) * 1280);
            #pragma unroll
            for (int s = 0; s < 2; s++) {        // two k16 steps
                unsigned a[4];
                LDSM4(a, a_addr0 + stg + (unsigned)(s * 32));
                #pragma unroll
                for (int g = 0; g < 3; g++)
                    mma16(c[g], a, &bf[g][s * 2]);
            }
        }

        // K-split reduction: warps 4-7 park partials, one sync, warps 0-3 finish.
        if (wid >= 4) {
            int base = (tid - 128) * 13;
            #pragma unroll
            for (int g = 0; g < 3; g++)
                #pragma unroll
                for (int s = 0; s < 4; s++) red[base + g * 4 + s] = c[g][s];
        }
        __syncthreads();

        if (wid < 4) {
            int base = tid * 13;
            float hn[4];
            #pragma unroll
            for (int s = 0; s < 4; s++) {
                int r = s >> 1, i = s & 1;
                int cc = tig * 2 + i;
                float mb = r ? mb1 : mb0;
                float gr = (c[0][s] + red[base + s])     * mb + bsh[cc];
                float gz = (c[1][s] + red[base + 4 + s]) * mb + bsh[8 + cc];
                float gn = (c[2][s] + red[base + 8 + s]) * mb + bsh[16 + cc];
                float rg = 1.f / (1.f + __expf(-(gpre[r * 6 + i] + gr)));
                float zg = 1.f / (1.f + __expf(-(gpre[r * 6 + 2 + i] + gz)));
                float ng = tanhf(gpre[r * 6 + 4 + i] + rg * gn);
                float hm = hloc[s] * mb;
                hn[s] = (1.f - zg) * ng + zg * hm;
                hloc[s] = hn[s];
            }
            int cb = col0 + tig * 2;
            __half2 p01 = __floats2half2_rn(hn[0], hn[1]);
            __half2 p23 = __floats2half2_rn(hn[2], hn[3]);
            __stcg((unsigned*)&hh_out[b0r * Hh + cb],       *(unsigned*)&p01);
            __stcg((unsigned*)&hh_out[(b0r + 8) * Hh + cb], *(unsigned*)&p23);
            __stcs((float2*)&outp[((size_t)b0r * Tt + t) * Hh + cb],       make_float2(hn[0], hn[1]));
            __stcs((float2*)&outp[((size_t)(b0r + 8) * Tt + t) * Hh + cb], make_float2(hn[2], hn[3]));
            if (t == Tt - 1) {                   // final fp32 h for the tail copy
                *(float2*)&g_h[0][b0r * Hh + cb]       = make_float2(hn[0], hn[1]);
                *(float2*)&g_h[0][(b0r + 8) * Hh + cb] = make_float2(hn[2], hn[3]);
            }
        }

        // grid barrier: release/acquire carries the h_out hand-off.
        __syncthreads();
        if (tid == 0) {
            unsigned target = (unsigned)(t + 1) * (unsigned)gridDim.x;
            unsigned one = 1u, v;
            asm volatile("red.release.gpu.global.add.u32 [%0], %1;"
                         :: "l"(&g_bar), "r"(one) : "memory");
            do {
                asm volatile("ld.acquire.gpu.global.u32 %0, [%1];"
                             : "=r"(v) : "l"(&g_bar) : "memory");
            } while (v < target);
        }
        __syncthreads();
    }
#undef ISSUE_CHUNK
}

__global__ void tail_kernel(float* __restrict__ dst) {
    int i = blockIdx.x * blockDim.x + threadIdx.x;
    if (i < Bb * Hh) dst[i] = g_h[0][i];   // final h written by rec at t=511
}

extern "C" void kernel_launch(void* const* d_in, const int* in_sizes, int n_in,
                              void* d_out, int out_size) {
    const float* input  = (const float*)d_in[0];
    const float* hidden = (const float*)d_in[1];
    const void*  done   = d_in[2];
    const float* W_ih   = (const float*)d_in[3];
    const float* W_hh   = (const float*)d_in[4];
    const float* b_ih   = (const float*)d_in[5];
    const float* b_hh   = (const float*)d_in[6];
    float* out = (float*)d_out;

    const int rec_smem = (24 * WSTRH + 8 * 2560) * 2;  // 90496 B dynamic

    cudaFuncSetAttribute(gemm1_kernel, cudaFuncAttributeMaxDynamicSharedMemorySize, 73728);
    cudaFuncSetAttribute(rec_kernel, cudaFuncAttributeMaxDynamicSharedMemorySize, rec_smem);

    detect_kernel<<<1, 256>>>((const unsigned*)done);
    prep_kernel<<<256, 256>>>(done, hidden);
    gemm1_kernel<<<dim3(G3 / 128, (Bb * Tt) / 128), 256, 73728>>>(input, W_ih, b_ih);
    rec_kernel<<<NCTA, 256, rec_smem>>>(W_hh, b_hh, out);
    if (out_size >= Bb * Tt * Hh + Bb * Hh)
        tail_kernel<<<64, 1024>>>(out + (size_t)Bb * Tt * Hh);
}

// round 14
// speedup vs baseline: 4.7298x; 1.2079x over previous
#include <cuda_runtime.h>
#include <cuda_fp16.h>

#define Bb 64
#define Tt 512
#define Ii 1024
#define Hh 1024
#define G3 3072
#define NCTA 128
#define WSTRH 1032   // rec W smem row stride (halfs): 2064B == 16 mod 128, 16B-aligned

// ---------------- scratch (static device globals; no allocation) ----------------
static __device__ float g_gi[(size_t)Tt * Bb * G3];   // [t][b][3H], b_ih folded in
static __device__ float g_h[2][Bb * Hh];              // fp32 h (init + final only)
static __device__ __half g_hh[2][Bb * Hh];            // fp16 ping-pong hidden state
static __device__ __half g_inh[(size_t)Bb * Tt * Ii]; // fp16 input mirror
static __device__ __half g_wih[G3 * Ii];              // fp16 W_ih mirror
static __device__ float g_dm[Tt * Bb];                // [t][b] mask: done?0:1
static __device__ int   g_kind;                       // 1 = done is 1-byte, 0 = 4-byte
static __device__ unsigned g_bar;                     // grid barrier counter

// ---------------- mma helpers ----------------
// fp16 m16n8k16: A 4 regs (2 f16 each), B 2 regs, C 4 f32
// C: c0=(gid,tig*2) c1=(gid,tig*2+1) c2=(gid+8,tig*2) c3=(gid+8,tig*2+1)
__device__ __forceinline__ void mma16(float* c, const unsigned* a, const unsigned* b) {
    asm("mma.sync.aligned.m16n8k16.row.col.f32.f16.f16.f32 "
        "{%0,%1,%2,%3}, {%4,%5,%6,%7}, {%8,%9}, {%0,%1,%2,%3};"
        : "+f"(c[0]), "+f"(c[1]), "+f"(c[2]), "+f"(c[3])
        : "r"(a[0]), "r"(a[1]), "r"(a[2]), "r"(a[3]), "r"(b[0]), "r"(b[1]));
}
#define LDSM4(r, addr)                                                            \
    asm volatile("ldmatrix.sync.aligned.m8n8.x4.shared.b16 {%0,%1,%2,%3}, [%4];"  \
                 : "=r"((r)[0]), "=r"((r)[1]), "=r"((r)[2]), "=r"((r)[3])         \
                 : "r"(addr))

// ---------------- done-dtype detection (graph-safe, device-side) ----------------
__global__ void detect_kernel(const unsigned* __restrict__ w) {
    __shared__ int hif, f32f;
    if (threadIdx.x == 0) { hif = 0; f32f = 0; }
    __syncthreads();
    for (int i = threadIdx.x; i < 8192; i += blockDim.x) {
        unsigned v = w[i];
        if (v == 0x3F800000u) atomicOr(&f32f, 1);
        else if (v & 0xFFFFFF00u) atomicOr(&hif, 1);
    }
    __syncthreads();
    if (threadIdx.x == 0) g_kind = (!f32f && hif) ? 1 : 0;
}

__global__ void prep_kernel(const void* __restrict__ done, const float* __restrict__ hidden) {
    int i = blockIdx.x * blockDim.x + threadIdx.x;
    if (i == 0) g_bar = 0u;
    if (i < Tt * Bb) {
        int t = i / Bb, b = i - t * Bb;
        int src = b * Tt + t;   // done is [B,T]
        bool d;
        if (g_kind == 1) d = ((const unsigned char*)done)[src] != 0;
        else             d = ((const unsigned*)done)[src] != 0u;
        g_dm[i] = d ? 0.f : 1.f;
    }
    if (i < Bb * Hh) {
        float hv = hidden[i];
        g_h[0][i] = hv;
        g_hh[0][i] = __float2half_rn(hv);
    }
}

// fp32 -> fp16 mirror (8 elements/thread); which: 0 = input->g_inh, 1 = W_ih->g_wih
__global__ void cvt_kernel(const float* __restrict__ src, int n8, int which) {
    int i = blockIdx.x * blockDim.x + threadIdx.x;
    if (i >= n8) return;
    size_t off = (size_t)i * 8;
    float4 v0 = *(const float4*)(src + off);
    float4 v1 = *(const float4*)(src + off + 4);
    __half2 h[4] = { __floats2half2_rn(v0.x, v0.y), __floats2half2_rn(v0.z, v0.w),
                     __floats2half2_rn(v1.x, v1.y), __floats2half2_rn(v1.z, v1.w) };
    __half* dst = which ? g_wih : g_inh;
    *(uint4*)(dst + off) = *(uint4*)h;
}

// ---------------- GEMM1 (fp16): gi[t][b][:] = input[b][t][:] @ W_ih^T + b_ih ----------------
// M=32768 (m=b*512+t), N=3072, K=1024. CTA 128x128x32, 8 warps (2x4), 4-stage
// cp.async pipeline, ldmatrix frags, m16n8k16 HMMA with fp32 accumulate.
__global__ void __launch_bounds__(256) gemm1_kernel(
    const __half* __restrict__ A, const __half* __restrict__ W,
    const float* __restrict__ bih)
{
    extern __shared__ __half smh[];
    const int tid = threadIdx.x;
    const int lane = tid & 31, wid = tid >> 5;
    const int gid = lane >> 2, tig = lane & 3;
    const int wm = (wid >> 2) * 64, wn = (wid & 3) * 32;
    const int n0 = blockIdx.x * 128, m0 = blockIdx.y * 128;  // N fastest -> W L2-resident
    const unsigned sbase = (unsigned)__cvta_generic_to_shared(smh);

    const int arow = (lane < 16) ? lane : (lane - 16);
    const int akoff = (lane >= 16) ? 8 : 0;       // halfs
    const int bnrow = lane & 7, bk8 = (lane >> 3) * 8;

    float c[4][4][4];
    #pragma unroll
    for (int i = 0; i < 4; i++)
        #pragma unroll
        for (int j = 0; j < 4; j++)
            #pragma unroll
            for (int k = 0; k < 4; k++) c[i][j][k] = 0.f;

// stage s: A at s*10240 B, B at 40960 + s*10240 B; rows padded to 40 halfs (80 B)
#define G1_ISSUE(kt) do {                                                        \
        int _s = (kt) & 3;                                                       \
        unsigned _ab = sbase + (unsigned)(_s * 10240);                           \
        unsigned _bb = _ab + 40960u;                                             \
        _Pragma("unroll")                                                        \
        for (int _j = 0; _j < 2; _j++) {                                         \
            int _i = _j * 256 + tid, _r = _i >> 2, _sg = _i & 3;                 \
            unsigned _off = (unsigned)(_r * 80 + _sg * 16);                      \
            const __half* _sa = A + (size_t)(m0 + _r) * Ii + (kt) * 32 + _sg * 8;\
            const __half* _sb = W + (size_t)(n0 + _r) * Ii + (kt) * 32 + _sg * 8;\
            asm volatile("cp.async.cg.shared.global [%0], [%1], 16;"             \
                         :: "r"(_ab + _off), "l"(_sa));                          \
            asm volatile("cp.async.cg.shared.global [%0], [%1], 16;"             \
                         :: "r"(_bb + _off), "l"(_sb));                          \
        }                                                                        \
        asm volatile("cp.async.commit_group;");                                  \
    } while (0)

    G1_ISSUE(0); G1_ISSUE(1); G1_ISSUE(2);

    #pragma unroll 1
    for (int kt = 0; kt < 32; ++kt) {
        if (kt < 30)       asm volatile("cp.async.wait_group 2;");
        else if (kt == 30) asm volatile("cp.async.wait_group 1;");
        else               asm volatile("cp.async.wait_group 0;");
        __syncthreads();
        if (kt + 3 < 32) G1_ISSUE(kt + 3);

        unsigned ab = sbase + (unsigned)((kt & 3) * 10240);
        unsigned bb = ab + 40960u;
        unsigned bf[4][4];
        #pragma unroll
        for (int in = 0; in < 4; in++)
            LDSM4(bf[in], bb + (unsigned)((wn + in * 8 + bnrow) * 80 + bk8 * 2));
        #pragma unroll
        for (int s = 0; s < 2; s++) {
            unsigned a[4][4];
            #pragma unroll
            for (int im = 0; im < 4; im++)
                LDSM4(a[im], ab + (unsigned)((wm + im * 16 + arow) * 80 + (akoff + s * 16) * 2));
            #pragma unroll
            for (int im = 0; im < 4; im++)
                #pragma unroll
                for (int in = 0; in < 4; in++)
                    mma16(c[im][in], a[im], &bf[in][s * 2]);
        }
    }
#undef G1_ISSUE

    // epilogue: +bias, transpose row m=(b*512+t) -> gi row (t*64+b)
    #pragma unroll
    for (int im = 0; im < 4; im++) {
        int mA = m0 + wm + im * 16 + gid;
        int mB = mA + 8;
        int rowA = (mA & 511) * Bb + (mA >> 9);
        int rowB = (mB & 511) * Bb + (mB >> 9);
        #pragma unroll
        for (int in = 0; in < 4; in++) {
            int cn = n0 + wn + in * 8 + tig * 2;
            float bx = bih[cn], by = bih[cn + 1];
            float2 v0 = make_float2(c[im][in][0] + bx, c[im][in][1] + by);
            float2 v1 = make_float2(c[im][in][2] + bx, c[im][in][3] + by);
            *(float2*)&g_gi[(size_t)rowA * G3 + cn] = v0;
            *(float2*)&g_gi[(size_t)rowB * G3 + cn] = v1;
        }
    }
}

// ---------------- persistent recurrent kernel: all 512 steps, fp16 MMA ----------------
__global__ void __launch_bounds__(256, 1) rec_kernel(
    const float* __restrict__ Whh, const float* __restrict__ bhh,
    float* __restrict__ outp)
{
    extern __shared__ unsigned dyn[];
    __half* wsh = (__half*)dyn;                  // 24 * WSTRH halfs
    __half* hsu = wsh + 24 * WSTRH;              // 8 warps x 4 stages x 16*40 halfs
    __shared__ float red[128 * 13];              // K-split partials
    __shared__ float bsh[24];

    const int tid = threadIdx.x;
    const int lane = tid & 31, wid = tid >> 5;
    const int gid = lane >> 2, tig = lane & 3;
    const int ks = wid >> 2;                     // K-split group 0/1
    const int mrow0 = (wid & 3) * 16;            // warp's 16 M-rows
    const int col0 = blockIdx.x * 8;
    const int b0r = mrow0 + gid;
    __half* hw = hsu + wid * 2560;               // this warp's 4-stage ring
    const unsigned hw_u32 = (unsigned)__cvta_generic_to_shared(hw);
    const unsigned ws_u32 = (unsigned)__cvta_generic_to_shared(wsh);

    // Load W slice once (fp16): row r = (gate r/8, col col0 + r%8), K=1024.
    for (int f = tid; f < 24 * 256; f += 256) {
        int r = f >> 8, cq = f & 255;
        float4 v = *(const float4*)&Whh[(size_t)((r >> 3) * Hh + col0 + (r & 7)) * Hh + cq * 4];
        *(__half2*)&wsh[r * WSTRH + cq * 4]     = __floats2half2_rn(v.x, v.y);
        *(__half2*)&wsh[r * WSTRH + cq * 4 + 2] = __floats2half2_rn(v.z, v.w);
    }
    if (tid < 24) bsh[tid] = bhh[(tid >> 3) * Hh + col0 + (tid & 7)];

    // ldmatrix per-lane addressing (same layouts as validated fp16 round)
    const int arow = (lane < 16) ? lane : (lane - 16);
    const int akoff = (lane >= 16) ? 8 : 0;
    const unsigned a_addr0 = hw_u32 + ((unsigned)(arow * 40 + akoff) << 1);
    const int b_nrow = lane & 7, b_k8 = (lane >> 3) * 8;
    unsigned b_addr[3];
    #pragma unroll
    for (int g = 0; g < 3; g++)
        b_addr[g] = ws_u32 + ((unsigned)((g * 8 + b_nrow) * WSTRH + b_k8) << 1);

    float hloc[4] = {0.f, 0.f, 0.f, 0.f};
    if (wid < 4) {
        int cb = col0 + tig * 2;
        hloc[0] = g_h[0][b0r * Hh + cb];
        hloc[1] = g_h[0][b0r * Hh + cb + 1];
        hloc[2] = g_h[0][(b0r + 8) * Hh + cb];
        hloc[3] = g_h[0][(b0r + 8) * Hh + cb + 1];
    }
    __syncthreads();

    const int kbase = ks * 512;                  // warp group's K offset (halfs)

#define ISSUE_CHUNK(ch) do {                                                     \
        unsigned _base = hw_u32 + (unsigned)((((ch) & 3) * 1280));               \
        _Pragma("unroll")                                                        \
        for (int _j = 0; _j < 2; _j++) {                                         \
            int _idx = _j * 32 + lane, _row = _idx >> 2, _seg = _idx & 3;        \
            unsigned _dst = _base + (unsigned)(_row * 80 + _seg * 16);           \
            const __half* _src = hh_in + (mrow0 + _row) * Hh + kbase + (ch) * 32 + _seg * 8; \
            asm volatile("cp.async.cg.shared.global [%0], [%1], 16;"             \
                         :: "r"(_dst), "l"(_src));                               \
        }                                                                        \
        asm volatile("cp.async.commit_group;");                                  \
    } while (0)

    // prefetch gi + done-mask for t=0
    float gpre[12], mb0 = 0.f, mb1 = 0.f;
    if (wid < 4) {
        int cb = col0 + tig * 2;
        const float* g0 = g_gi + (size_t)b0r * G3;
        const float* g1 = g_gi + (size_t)(b0r + 8) * G3;
        #pragma unroll
        for (int g = 0; g < 3; g++) {
            float2 p0 = __ldcg((const float2*)(g0 + g * Hh + cb));
            float2 p1 = __ldcg((const float2*)(g1 + g * Hh + cb));
            gpre[g * 2] = p0.x;     gpre[g * 2 + 1] = p0.y;
            gpre[6 + g * 2] = p1.x; gpre[6 + g * 2 + 1] = p1.y;
        }
        mb0 = __ldg(&g_dm[b0r]);
        mb1 = __ldg(&g_dm[b0r + 8]);
    }

    for (int t = 0; t < Tt; ++t) {
        const __half* __restrict__ hh_in  = g_hh[t & 1];
        __half* __restrict__       hh_out = g_hh[(t + 1) & 1];

        ISSUE_CHUNK(0); ISSUE_CHUNK(1); ISSUE_CHUNK(2);

        float c[3][4];
        #pragma unroll
        for (int g = 0; g < 3; g++)
            #pragma unroll
            for (int s = 0; s < 4; s++) c[g][s] = 0.f;

        #pragma unroll 1
        for (int i = 0; i < 16; ++i) {
            if (i < 14)       asm volatile("cp.async.wait_group 2;");
            else if (i == 14) asm volatile("cp.async.wait_group 1;");
            else              asm volatile("cp.async.wait_group 0;");
            if (i + 3 < 16) ISSUE_CHUNK(i + 3);

            const int kb = kbase + i * 32;       // halfs
            unsigned bf[3][4];
            #pragma unroll
            for (int g = 0; g < 3; g++)
                LDSM4(bf[g], b_addr[g] + ((unsigned)kb << 1));
            const unsigned stg = (unsigned)((i & 3) * 1280);
            #pragma unroll
            for (int s = 0; s < 2; s++) {
                unsigned a[4];
                LDSM4(a, a_addr0 + stg + (unsigned)(s * 32));
                #pragma unroll
                for (int g = 0; g < 3; g++)
                    mma16(c[g], a, &bf[g][s * 2]);
            }
        }

        // K-split reduction
        if (wid >= 4) {
            int base = (tid - 128) * 13;
            #pragma unroll
            for (int g = 0; g < 3; g++)
                #pragma unroll
                for (int s = 0; s < 4; s++) red[base + g * 4 + s] = c[g][s];
        }
        __syncthreads();

        if (wid < 4) {
            int base = tid * 13;
            float hn[4];
            #pragma unroll
            for (int s = 0; s < 4; s++) {
                int r = s >> 1, i = s & 1;
                int cc = tig * 2 + i;
                float mb = r ? mb1 : mb0;
                float gr = (c[0][s] + red[base + s])     * mb + bsh[cc];
                float gz = (c[1][s] + red[base + 4 + s]) * mb + bsh[8 + cc];
                float gn = (c[2][s] + red[base + 8 + s]) * mb + bsh[16 + cc];
                float rg = __fdividef(1.f, 1.f + __expf(-(gpre[r * 6 + i] + gr)));
                float zg = __fdividef(1.f, 1.f + __expf(-(gpre[r * 6 + 2 + i] + gz)));
                float xa = gpre[r * 6 + 4 + i] + rg * gn;
                float ng = 1.f - __fdividef(2.f, __expf(2.f * xa) + 1.f);
                float hm = hloc[s] * mb;
                hn[s] = (1.f - zg) * ng + zg * hm;
                hloc[s] = hn[s];
            }
            int cb = col0 + tig * 2;
            __half2 p01 = __floats2half2_rn(hn[0], hn[1]);
            __half2 p23 = __floats2half2_rn(hn[2], hn[3]);
            __stcg((unsigned*)&hh_out[b0r * Hh + cb],       *(unsigned*)&p01);
            __stcg((unsigned*)&hh_out[(b0r + 8) * Hh + cb], *(unsigned*)&p23);
            __stcs((float2*)&outp[((size_t)b0r * Tt + t) * Hh + cb],       make_float2(hn[0], hn[1]));
            __stcs((float2*)&outp[((size_t)(b0r + 8) * Tt + t) * Hh + cb], make_float2(hn[2], hn[3]));
            if (t == Tt - 1) {
                *(float2*)&g_h[0][b0r * Hh + cb]       = make_float2(hn[0], hn[1]);
                *(float2*)&g_h[0][(b0r + 8) * Hh + cb] = make_float2(hn[2], hn[3]);
            }
        }

        // prefetch gi + mask for t+1 (independent of h) — hides under the barrier
        if (wid < 4 && t + 1 < Tt) {
            const float* gi_n = g_gi + (size_t)(t + 1) * (Bb * G3);
            int cb = col0 + tig * 2;
            const float* g0 = gi_n + (size_t)b0r * G3;
            const float* g1 = gi_n + (size_t)(b0r + 8) * G3;
            #pragma unroll
            for (int g = 0; g < 3; g++) {
                float2 p0 = __ldcg((const float2*)(g0 + g * Hh + cb));
                float2 p1 = __ldcg((const float2*)(g1 + g * Hh + cb));
                gpre[g * 2] = p0.x;     gpre[g * 2 + 1] = p0.y;
                gpre[6 + g * 2] = p1.x; gpre[6 + g * 2 + 1] = p1.y;
            }
            mb0 = __ldg(&g_dm[(t + 1) * Bb + b0r]);
            mb1 = __ldg(&g_dm[(t + 1) * Bb + b0r + 8]);
        }

        // grid barrier: release/acquire carries the h_out hand-off.
        __syncthreads();
        if (tid == 0) {
            unsigned target = (unsigned)(t + 1) * (unsigned)gridDim.x;
            unsigned one = 1u, v;
            asm volatile("red.release.gpu.global.add.u32 [%0], %1;"
                         :: "l"(&g_bar), "r"(one) : "memory");
            do {
                asm volatile("ld.acquire.gpu.global.u32 %0, [%1];"
                             : "=r"(v) : "l"(&g_bar) : "memory");
            } while (v < target);
        }
        __syncthreads();
    }
#undef ISSUE_CHUNK
}

__global__ void tail_kernel(float* __restrict__ dst) {
    int i = blockIdx.x * blockDim.x + threadIdx.x;
    if (i < Bb * Hh) dst[i] = g_h[0][i];   // final h written by rec at t=511
}

extern "C" void kernel_launch(void* const* d_in, const int* in_sizes, int n_in,
                              void* d_out, int out_size) {
    const float* input  = (const float*)d_in[0];
    const float* hidden = (const float*)d_in[1];
    const void*  done   = d_in[2];
    const float* W_ih   = (const float*)d_in[3];
    const float* W_hh   = (const float*)d_in[4];
    const float* b_ih   = (const float*)d_in[5];
    const float* b_hh   = (const float*)d_in[6];
    float* out = (float*)d_out;

    const int rec_smem   = (24 * WSTRH + 8 * 2560) * 2;  // 90496 B
    const int gemm1_smem = 81920;                        // 4 stages x (A+B) fp16

    cudaFuncSetAttribute(gemm1_kernel, cudaFuncAttributeMaxDynamicSharedMemorySize, gemm1_smem);
    cudaFuncSetAttribute(rec_kernel, cudaFuncAttributeMaxDynamicSharedMemorySize, rec_smem);

    detect_kernel<<<1, 256>>>((const unsigned*)done);
    prep_kernel<<<256, 256>>>(done, hidden);
    {
        int n8i = (Bb * Tt * Ii) / 8;   // 4194304
        int n8w = (G3 * Ii) / 8;        // 393216
        cvt_kernel<<<(n8i + 255) / 256, 256>>>(input, n8i, 0);
        cvt_kernel<<<(n8w + 255) / 256, 256>>>(W_ih, n8w, 1);
    }
    {
        // device-pointer access to the fp16 mirrors for gemm1 args
        void* pin = nullptr; void* pw = nullptr;
        cudaGetSymbolAddress(&pin, g_inh);
        cudaGetSymbolAddress(&pw, g_wih);
        gemm1_kernel<<<dim3(G3 / 128, (Bb * Tt) / 128), 256, gemm1_smem>>>(
            (const __half*)pin, (const __half*)pw, b_ih);
    }
    rec_kernel<<<NCTA, 256, rec_smem>>>(W_hh, b_hh, out);
    if (out_size >= Bb * Tt * Hh + Bb * Hh)
        tail_kernel<<<64, 1024>>>(out + (size_t)Bb * Tt * Hh);
}